// round 15
// baseline (speedup 1.0000x reference)
#include <cuda_runtime.h>
#include <cuda_bf16.h>
#include <math.h>
#include <stdint.h>

#define V_ 371
#define E_ 512
#define H_ 8
#define L_ 8
#define B_ 4
#define T_ 1024
#define D_ 64

// ---------------- scratch (static device globals; no allocation) ----------------
__device__ __align__(256) float g_x[B_ * T_ * E_];
__device__ __align__(256) __nv_bfloat16 g_lnh[B_ * T_ * E_];
__device__ __align__(256) __nv_bfloat16 g_lnl[B_ * T_ * E_];
__device__ __align__(256) __nv_bfloat16 g_qh[B_ * H_ * T_ * D_];
__device__ __align__(256) __nv_bfloat16 g_ql[B_ * H_ * T_ * D_];
__device__ __align__(256) __nv_bfloat16 g_kh[B_ * H_ * T_ * D_];
__device__ __align__(256) __nv_bfloat16 g_kl[B_ * H_ * T_ * D_];
__device__ __align__(256) __nv_bfloat16 g_vh[B_ * H_ * T_ * D_];   // v row-major [bh,t,d]
__device__ __align__(256) __nv_bfloat16 g_vl[B_ * H_ * T_ * D_];
__device__ __align__(256) __nv_bfloat16 g_yh[B_ * T_ * E_];
__device__ __align__(256) __nv_bfloat16 g_yl[B_ * T_ * E_];
__device__ __align__(256) __nv_bfloat16 g_h2h[B_ * T_ * 4 * E_];
__device__ __align__(256) __nv_bfloat16 g_h2l[B_ * T_ * 4 * E_];

#define OFF_AW 0
#define SZ_AW (L_ * 3 * E_ * E_)
#define OFF_PW (OFF_AW + SZ_AW)
#define SZ_PW (L_ * E_ * E_)
#define OFF_FW (OFF_PW + SZ_PW)
#define SZ_FW (L_ * 4 * E_ * E_)
#define OFF_FPW (OFF_FW + SZ_FW)
#define SZ_FPW (L_ * E_ * 4 * E_)
#define OFF_WTE (OFF_FPW + SZ_FPW)
#define SZ_WTE_PAD (384 * E_)
#define SZ_WALL (OFF_WTE + SZ_WTE_PAD)
__device__ __align__(256) __nv_bfloat16 g_wh[SZ_WALL];
__device__ __align__(256) __nv_bfloat16 g_wl[SZ_WALL];

// =================================================================
//                        small helpers
// =================================================================
__device__ __forceinline__ uint32_t smem_u32(const void* p) {
    uint32_t a;
    asm("{ .reg .u64 t; cvta.to.shared.u64 t, %1; cvt.u32.u64 %0, t; }" : "=r"(a) : "l"(p));
    return a;
}
__device__ __forceinline__ void cpa16(void* sdst, const void* gsrc) {
    uint32_t s = smem_u32(sdst);
    asm volatile("cp.async.cg.shared.global [%0], [%1], 16;" :: "r"(s), "l"(gsrc));
}
__device__ __forceinline__ void mma_bf16(float* c, const uint32_t* a, const uint32_t* b) {
    asm volatile(
        "mma.sync.aligned.m16n8k16.row.col.f32.bf16.bf16.f32 "
        "{%0,%1,%2,%3}, {%4,%5,%6,%7}, {%8,%9}, {%0,%1,%2,%3};"
        : "+f"(c[0]), "+f"(c[1]), "+f"(c[2]), "+f"(c[3])
        : "r"(a[0]), "r"(a[1]), "r"(a[2]), "r"(a[3]), "r"(b[0]), "r"(b[1]));
}
__device__ __forceinline__ void ldsm_x4(uint32_t* r, uint32_t addr) {
    asm volatile("ldmatrix.sync.aligned.m8n8.x4.shared.b16 {%0,%1,%2,%3}, [%4];"
                 : "=r"(r[0]), "=r"(r[1]), "=r"(r[2]), "=r"(r[3]) : "r"(addr));
}
__device__ __forceinline__ void ldsm_x4_t(uint32_t* r, uint32_t addr) {
    asm volatile("ldmatrix.sync.aligned.m8n8.x4.trans.shared.b16 {%0,%1,%2,%3}, [%4];"
                 : "=r"(r[0]), "=r"(r[1]), "=r"(r[2]), "=r"(r[3]) : "r"(addr));
}
__device__ __forceinline__ void split2(float x0, float x1, uint32_t& hp, uint32_t& lp) {
    __nv_bfloat16 h0 = __float2bfloat16(x0), h1 = __float2bfloat16(x1);
    __nv_bfloat162 hh(h0, h1);
    hp = *reinterpret_cast<uint32_t*>(&hh);
    __nv_bfloat16 l0 = __float2bfloat16(x0 - __bfloat162float(h0));
    __nv_bfloat16 l1 = __float2bfloat16(x1 - __bfloat162float(h1));
    __nv_bfloat162 ll(l0, l1);
    lp = *reinterpret_cast<uint32_t*>(&ll);
}

// =================================================================
//   HMMA split-bf16 GEMM 128x128 (R12-proven)
// =================================================================
#define SROW 40
#define STILE (128 * SROW)
#define SMEM_MMA_BYTES (2 * 4 * STILE * 2)

template <int EPI>
__global__ void __launch_bounds__(256, 2)
gemm_mma(const __nv_bfloat16* __restrict__ Ah, const __nv_bfloat16* __restrict__ Al,
         const __nv_bfloat16* __restrict__ Bh, const __nv_bfloat16* __restrict__ Bl,
         const float* __restrict__ Add, float* __restrict__ C,
         int N, int K, int ldc) {
    extern __shared__ __nv_bfloat16 smh[];
    int tid = threadIdx.x;
    int wid = tid >> 5, lane = tid & 31;
    int wm = wid >> 1, wn = wid & 1;
    int lr = lane >> 2, lc = lane & 3;

    int m0 = blockIdx.y * 128;
    int n0 = blockIdx.x * 128;

    const __nv_bfloat16* srcs[4] = {
        Ah + (size_t)m0 * K, Al + (size_t)m0 * K,
        Bh + (size_t)n0 * K, Bl + (size_t)n0 * K};

    int lrow = tid >> 1;
    int q0 = (tid & 1) * 2;
    int nch = K >> 5;

    uint32_t sbu = smem_u32(smh);
    uint32_t a_lane = (uint32_t)((lane & 15) * SROW + (lane >> 4) * 8);
    uint32_t b_lane = (uint32_t)((((lane >> 4) << 3) + (lane & 7)) * SROW + ((lane >> 3) & 1) * 8);

    {
#pragma unroll
        for (int t = 0; t < 4; t++) {
            const __nv_bfloat16* sp = srcs[t] + (size_t)lrow * K;
            __nv_bfloat16* dp = smh + t * STILE + lrow * SROW;
            cpa16(dp + q0 * 8, sp + q0 * 8);
            cpa16(dp + (q0 + 1) * 8, sp + (q0 + 1) * 8);
        }
        asm volatile("cp.async.commit_group;");
    }

    float acc[2][8][4];
#pragma unroll
    for (int i = 0; i < 2; i++)
#pragma unroll
        for (int j = 0; j < 8; j++)
#pragma unroll
            for (int r = 0; r < 4; r++) acc[i][j][r] = 0.f;

    for (int c = 0; c < nch; c++) {
        if (c + 1 < nch) {
            int k0 = (c + 1) << 5;
            __nv_bfloat16* sb = smh + ((c + 1) & 1) * 4 * STILE;
#pragma unroll
            for (int t = 0; t < 4; t++) {
                const __nv_bfloat16* sp = srcs[t] + (size_t)lrow * K + k0;
                __nv_bfloat16* dp = sb + t * STILE + lrow * SROW;
                cpa16(dp + q0 * 8, sp + q0 * 8);
                cpa16(dp + (q0 + 1) * 8, sp + (q0 + 1) * 8);
            }
            asm volatile("cp.async.commit_group;");
            asm volatile("cp.async.wait_group 1;");
        } else {
            asm volatile("cp.async.wait_group 0;");
        }
        __syncthreads();

        uint32_t tbu = sbu + (uint32_t)((c & 1) * 4 * STILE) * 2u;
        uint32_t pAh = tbu;
        uint32_t pAl = tbu + STILE * 2u;
        uint32_t pBh = tbu + 2u * STILE * 2u;
        uint32_t pBl = tbu + 3u * STILE * 2u;

#pragma unroll
        for (int ks = 0; ks < 2; ks++) {
            uint32_t kso = (uint32_t)(ks * 16) * 2u;
            uint32_t ah[2][4], al[2][4], bh[8][2], bl[8][2];
#pragma unroll
            for (int i = 0; i < 2; i++) {
                uint32_t off = (uint32_t)((wm * 32 + i * 16) * SROW) * 2u + a_lane * 2u + kso;
                ldsm_x4(ah[i], pAh + off);
                ldsm_x4(al[i], pAl + off);
            }
#pragma unroll
            for (int jp = 0; jp < 4; jp++) {
                uint32_t off = (uint32_t)((wn * 64 + jp * 16) * SROW) * 2u + b_lane * 2u + kso;
                uint32_t q[4];
                ldsm_x4(q, pBh + off);
                bh[2 * jp][0] = q[0]; bh[2 * jp][1] = q[1];
                bh[2 * jp + 1][0] = q[2]; bh[2 * jp + 1][1] = q[3];
                ldsm_x4(q, pBl + off);
                bl[2 * jp][0] = q[0]; bl[2 * jp][1] = q[1];
                bl[2 * jp + 1][0] = q[2]; bl[2 * jp + 1][1] = q[3];
            }
#pragma unroll
            for (int i = 0; i < 2; i++)
#pragma unroll
                for (int j = 0; j < 8; j++) mma_bf16(acc[i][j], ah[i], bh[j]);
#pragma unroll
            for (int i = 0; i < 2; i++)
#pragma unroll
                for (int j = 0; j < 8; j++) mma_bf16(acc[i][j], ah[i], bl[j]);
#pragma unroll
            for (int i = 0; i < 2; i++)
#pragma unroll
                for (int j = 0; j < 8; j++) mma_bf16(acc[i][j], al[i], bh[j]);
        }
        __syncthreads();
    }

#pragma unroll
    for (int i = 0; i < 2; i++) {
#pragma unroll
        for (int half = 0; half < 2; half++) {
            int r = m0 + wm * 32 + i * 16 + lr + half * 8;
#pragma unroll
            for (int j = 0; j < 8; j++) {
                int col = n0 + wn * 64 + j * 8 + lc * 2;
                float v0 = acc[i][j][half * 2 + 0];
                float v1 = acc[i][j][half * 2 + 1];
                if (EPI == 0) {
                    float* crow = C + (size_t)r * ldc;
                    if (col < N) crow[col] = v0;
                    if (col + 1 < N) crow[col + 1] = v1;
                } else if (EPI == 2) {
                    const float* arow = Add + (size_t)r * ldc + col;
                    float2 a = *reinterpret_cast<const float2*>(arow);
                    *reinterpret_cast<float2*>(C + (size_t)r * ldc + col) =
                        make_float2(v0 + a.x, v1 + a.y);
                } else if (EPI == 3) {
                    int b = r >> 10, t = r & 1023;
                    int seg = col >> 9, cc = col & 511;
                    int hh = cc >> 6, d = cc & 63;
                    size_t bht = (((size_t)(b * 8 + hh)) << 10) + t;
                    uint32_t hp, lp;
                    if (seg == 0) {
                        v0 *= 0.125f; v1 *= 0.125f;
                        split2(v0, v1, hp, lp);
                        *reinterpret_cast<uint32_t*>(g_qh + bht * 64 + d) = hp;
                        *reinterpret_cast<uint32_t*>(g_ql + bht * 64 + d) = lp;
                    } else if (seg == 1) {
                        split2(v0, v1, hp, lp);
                        *reinterpret_cast<uint32_t*>(g_kh + bht * 64 + d) = hp;
                        *reinterpret_cast<uint32_t*>(g_kl + bht * 64 + d) = lp;
                    } else {
                        split2(v0, v1, hp, lp);
                        *reinterpret_cast<uint32_t*>(g_vh + bht * 64 + d) = hp;
                        *reinterpret_cast<uint32_t*>(g_vl + bht * 64 + d) = lp;
                    }
                } else if (EPI == 4) {
                    v0 = 0.5f * v0 * (1.f + erff(v0 * 0.70710678118654752440f));
                    v1 = 0.5f * v1 * (1.f + erff(v1 * 0.70710678118654752440f));
                    uint32_t hp, lp; split2(v0, v1, hp, lp);
                    size_t off = (size_t)r * 2048 + col;
                    *reinterpret_cast<uint32_t*>(g_h2h + off) = hp;
                    *reinterpret_cast<uint32_t*>(g_h2l + off) = lp;
                }
            }
        }
    }
}

// =================================================================
//    Fused flash attention (R14-proven: masked-warp skip)
// =================================================================
#define AT_SMEM 73728

__device__ __forceinline__ void at_load_kv(
    __nv_bfloat16* sm, int tid,
    const __nv_bfloat16* kh, const __nv_bfloat16* kl,
    const __nv_bfloat16* vh, const __nv_bfloat16* vl,
    size_t qkoff, int kb, int bsel) {
    int row = tid >> 1;
    int q0 = (tid & 1) * 4;
    __nv_bfloat16* base = sm + bsel * 18432;
    const __nv_bfloat16* gkh = kh + qkoff + (size_t)(kb * 64 + row) * 64;
    const __nv_bfloat16* gkl = kl + qkoff + (size_t)(kb * 64 + row) * 64;
    const __nv_bfloat16* gvh = vh + qkoff + (size_t)(kb * 64 + row) * 64;
    const __nv_bfloat16* gvl = vl + qkoff + (size_t)(kb * 64 + row) * 64;
#pragma unroll
    for (int c = 0; c < 4; c++) {
        cpa16(base + row * 72 + (q0 + c) * 8, gkh + (q0 + c) * 8);
        cpa16(base + 4608 + row * 72 + (q0 + c) * 8, gkl + (q0 + c) * 8);
        cpa16(base + 9216 + row * 72 + (q0 + c) * 8, gvh + (q0 + c) * 8);
        cpa16(base + 13824 + row * 72 + (q0 + c) * 8, gvl + (q0 + c) * 8);
    }
}

__global__ void __launch_bounds__(128)
flash_attn(const __nv_bfloat16* __restrict__ qh, const __nv_bfloat16* __restrict__ ql,
           const __nv_bfloat16* __restrict__ kh, const __nv_bfloat16* __restrict__ kl,
           const __nv_bfloat16* __restrict__ vh, const __nv_bfloat16* __restrict__ vl,
           __nv_bfloat16* __restrict__ yh, __nv_bfloat16* __restrict__ yl) {
    extern __shared__ __nv_bfloat16 sm[];
    int tid = threadIdx.x, w = tid >> 5, lane = tid & 31;
    int lr = lane >> 2, lc = lane & 3;
    int qb = 7 - blockIdx.x;
    int bh = blockIdx.y;
    const size_t qkoff = (size_t)bh << 16;

    uint32_t smu = smem_u32(sm);
    uint32_t b_lane72 = (uint32_t)((((lane >> 4) << 3) + (lane & 7)) * 72 + ((lane >> 3) & 1) * 8);
    uint32_t a_lane72 = (uint32_t)((lane & 15) * 72 + (lane >> 4) * 8);

    {
        const __nv_bfloat16* gq = qh + qkoff + (size_t)(qb * 128 + tid) * 64;
        const __nv_bfloat16* gq2 = ql + qkoff + (size_t)(qb * 128 + tid) * 64;
        __nv_bfloat16* dh = sm + tid * 72;
        __nv_bfloat16* dl = sm + 9216 + tid * 72;
#pragma unroll
        for (int q = 0; q < 8; q++) { cpa16(dh + q * 8, gq + q * 8); cpa16(dl + q * 8, gq2 + q * 8); }
        asm volatile("cp.async.commit_group;");
        asm volatile("cp.async.wait_group 0;");
        __syncthreads();
    }
    uint32_t qfh[2][4][4], qfl[2][4][4];
#pragma unroll
    for (int mt = 0; mt < 2; mt++)
#pragma unroll
        for (int kk = 0; kk < 4; kk++) {
            int r = w * 32 + mt * 16 + lr;
            const __nv_bfloat16* p = sm + r * 72 + kk * 16 + lc * 2;
            qfh[mt][kk][0] = *(const uint32_t*)p;
            qfh[mt][kk][1] = *(const uint32_t*)(p + 8 * 72);
            qfh[mt][kk][2] = *(const uint32_t*)(p + 8);
            qfh[mt][kk][3] = *(const uint32_t*)(p + 8 * 72 + 8);
            const __nv_bfloat16* p2 = p + 9216;
            qfl[mt][kk][0] = *(const uint32_t*)p2;
            qfl[mt][kk][1] = *(const uint32_t*)(p2 + 8 * 72);
            qfl[mt][kk][2] = *(const uint32_t*)(p2 + 8);
            qfl[mt][kk][3] = *(const uint32_t*)(p2 + 8 * 72 + 8);
        }
    __syncthreads();

    float m_[4], l_[4], o[2][8][4];
#pragma unroll
    for (int s = 0; s < 4; s++) { m_[s] = -1e30f; l_[s] = 0.f; }
#pragma unroll
    for (int i = 0; i < 2; i++)
#pragma unroll
        for (int j = 0; j < 8; j++)
#pragma unroll
            for (int r = 0; r < 4; r++) o[i][j][r] = 0.f;

    int nkb = 2 * qb + 2;
    at_load_kv(sm, tid, kh, kl, vh, vl, qkoff, 0, 1);
    asm volatile("cp.async.commit_group;");

    for (int kb = 0; kb < nkb; kb++) {
        if (kb + 1 < nkb) {
            at_load_kv(sm, tid, kh, kl, vh, vl, qkoff, kb + 1, kb & 1);
            asm volatile("cp.async.commit_group;");
            asm volatile("cp.async.wait_group 1;");
        } else {
            asm volatile("cp.async.wait_group 0;");
        }
        __syncthreads();

        bool active = !(kb == 2 * qb + 1 && w < 2);
        bool need_mask = (kb == 2 * qb && w < 2) || (kb == 2 * qb + 1 && w >= 2);

        if (active) {
            uint32_t bb = smu + (uint32_t)(((kb + 1) & 1) * 18432) * 2u;
            uint32_t pKh = bb;
            uint32_t pKl = bb + 4608 * 2u;
            uint32_t pVh = bb + 9216 * 2u;
            uint32_t pVl = bb + 13824 * 2u;

            float s[2][8][4];
#pragma unroll
            for (int i = 0; i < 2; i++)
#pragma unroll
                for (int j = 0; j < 8; j++)
#pragma unroll
                    for (int r = 0; r < 4; r++) s[i][j][r] = 0.f;

#pragma unroll
            for (int kk = 0; kk < 4; kk++) {
                uint32_t kso = (uint32_t)(kk * 16) * 2u;
                uint32_t bh_[8][2], bl_[8][2];
#pragma unroll
                for (int jp = 0; jp < 4; jp++) {
                    uint32_t off = (uint32_t)(jp * 16 * 72) * 2u + b_lane72 * 2u + kso;
                    uint32_t q[4];
                    ldsm_x4(q, pKh + off);
                    bh_[2 * jp][0] = q[0]; bh_[2 * jp][1] = q[1];
                    bh_[2 * jp + 1][0] = q[2]; bh_[2 * jp + 1][1] = q[3];
                    ldsm_x4(q, pKl + off);
                    bl_[2 * jp][0] = q[0]; bl_[2 * jp][1] = q[1];
                    bl_[2 * jp + 1][0] = q[2]; bl_[2 * jp + 1][1] = q[3];
                }
#pragma unroll
                for (int jn = 0; jn < 8; jn++)
#pragma unroll
                    for (int mt = 0; mt < 2; mt++) {
                        mma_bf16(s[mt][jn], qfh[mt][kk], bh_[jn]);
                        mma_bf16(s[mt][jn], qfh[mt][kk], bl_[jn]);
                        mma_bf16(s[mt][jn], qfl[mt][kk], bh_[jn]);
                    }
            }

            if (need_mask) {
                int rowbase = qb * 128 + w * 32;
                int colbase = kb * 64;
#pragma unroll
                for (int mt = 0; mt < 2; mt++)
#pragma unroll
                    for (int jn = 0; jn < 8; jn++)
#pragma unroll
                        for (int idx = 0; idx < 4; idx++) {
                            int row = rowbase + mt * 16 + lr + ((idx >> 1) << 3);
                            int col = colbase + jn * 8 + lc * 2 + (idx & 1);
                            if (col > row) s[mt][jn][idx] = -1e30f;
                        }
            }

            float scl[4];
#pragma unroll
            for (int sl = 0; sl < 4; sl++) {
                int mt = sl >> 1, h = sl & 1;
                float cm = -1e30f;
#pragma unroll
                for (int jn = 0; jn < 8; jn++)
                    cm = fmaxf(cm, fmaxf(s[mt][jn][h * 2], s[mt][jn][h * 2 + 1]));
                cm = fmaxf(cm, __shfl_xor_sync(0xffffffffu, cm, 1));
                cm = fmaxf(cm, __shfl_xor_sync(0xffffffffu, cm, 2));
                float mnew = fmaxf(m_[sl], cm);
                scl[sl] = __expf(m_[sl] - mnew);
                m_[sl] = mnew;
            }
            float rs[4] = {0.f, 0.f, 0.f, 0.f};
#pragma unroll
            for (int mt = 0; mt < 2; mt++)
#pragma unroll
                for (int jn = 0; jn < 8; jn++) {
                    s[mt][jn][0] = __expf(s[mt][jn][0] - m_[mt * 2]);
                    s[mt][jn][1] = __expf(s[mt][jn][1] - m_[mt * 2]);
                    s[mt][jn][2] = __expf(s[mt][jn][2] - m_[mt * 2 + 1]);
                    s[mt][jn][3] = __expf(s[mt][jn][3] - m_[mt * 2 + 1]);
                    rs[mt * 2] += s[mt][jn][0] + s[mt][jn][1];
                    rs[mt * 2 + 1] += s[mt][jn][2] + s[mt][jn][3];
                }
#pragma unroll
            for (int sl = 0; sl < 4; sl++) {
                rs[sl] += __shfl_xor_sync(0xffffffffu, rs[sl], 1);
                rs[sl] += __shfl_xor_sync(0xffffffffu, rs[sl], 2);
                l_[sl] = l_[sl] * scl[sl] + rs[sl];
            }
#pragma unroll
            for (int mt = 0; mt < 2; mt++)
#pragma unroll
                for (int jn = 0; jn < 8; jn++) {
                    o[mt][jn][0] *= scl[mt * 2];
                    o[mt][jn][1] *= scl[mt * 2];
                    o[mt][jn][2] *= scl[mt * 2 + 1];
                    o[mt][jn][3] *= scl[mt * 2 + 1];
                }

#pragma unroll
            for (int kk = 0; kk < 4; kk++) {
                uint32_t pah[2][4], pal[2][4];
#pragma unroll
                for (int mt = 0; mt < 2; mt++) {
                    split2(s[mt][2 * kk][0], s[mt][2 * kk][1], pah[mt][0], pal[mt][0]);
                    split2(s[mt][2 * kk][2], s[mt][2 * kk][3], pah[mt][1], pal[mt][1]);
                    split2(s[mt][2 * kk + 1][0], s[mt][2 * kk + 1][1], pah[mt][2], pal[mt][2]);
                    split2(s[mt][2 * kk + 1][2], s[mt][2 * kk + 1][3], pah[mt][3], pal[mt][3]);
                }
                uint32_t vh_[8][2], vl_[8][2];
#pragma unroll
                for (int jp = 0; jp < 4; jp++) {
                    uint32_t off = (uint32_t)(kk * 16 * 72 + jp * 16) * 2u + a_lane72 * 2u;
                    uint32_t q[4];
                    ldsm_x4_t(q, pVh + off);
                    vh_[2 * jp][0] = q[0]; vh_[2 * jp][1] = q[1];
                    vh_[2 * jp + 1][0] = q[2]; vh_[2 * jp + 1][1] = q[3];
                    ldsm_x4_t(q, pVl + off);
                    vl_[2 * jp][0] = q[0]; vl_[2 * jp][1] = q[1];
                    vl_[2 * jp + 1][0] = q[2]; vl_[2 * jp + 1][1] = q[3];
                }
#pragma unroll
                for (int jn = 0; jn < 8; jn++)
#pragma unroll
                    for (int mt = 0; mt < 2; mt++) {
                        mma_bf16(o[mt][jn], pah[mt], vh_[jn]);
                        mma_bf16(o[mt][jn], pah[mt], vl_[jn]);
                        mma_bf16(o[mt][jn], pal[mt], vh_[jn]);
                    }
            }
        }
        __syncthreads();
    }

    int b = bh >> 3, hhd = bh & 7;
#pragma unroll
    for (int mt = 0; mt < 2; mt++)
#pragma unroll
        for (int h = 0; h < 2; h++) {
            int t = qb * 128 + w * 32 + mt * 16 + lr + h * 8;
            size_t row = (size_t)(b * 1024 + t) * 512 + hhd * 64;
            float inv = 1.f / l_[mt * 2 + h];
#pragma unroll
            for (int jn = 0; jn < 8; jn++) {
                int col = jn * 8 + lc * 2;
                float x0 = o[mt][jn][h * 2] * inv;
                float x1 = o[mt][jn][h * 2 + 1] * inv;
                uint32_t hp, lp;
                split2(x0, x1, hp, lp);
                *reinterpret_cast<uint32_t*>(yh + row + col) = hp;
                *reinterpret_cast<uint32_t*>(yl + row + col) = lp;
            }
        }
}

// =================================================================
//   Fused weight conversion: all 4 transposed splits + wte split
//   in ONE launch (job table by blockIdx.x).
//   AW: 6144 tiles | PW: 2048 | FW: 8192 | FPW: 8192 | WTE: 186 flat
// =================================================================
#define NB_AW 6144
#define NB_PW 2048
#define NB_FW 8192
#define NB_FPW 8192
#define NB_TILES (NB_AW + NB_PW + NB_FW + NB_FPW)
#define NB_WTE ((V_ * E_ / 4 + 255) / 256)
#define NB_ALL (NB_TILES + NB_WTE)

__global__ void __launch_bounds__(256)
split_weights(const float* __restrict__ aw, const float* __restrict__ pw,
              const float* __restrict__ fw, const float* __restrict__ fpw,
              const float* __restrict__ wte,
              __nv_bfloat16* __restrict__ wh, __nv_bfloat16* __restrict__ wl) {
    int bid = blockIdx.x;
    int tx = threadIdx.x, ty = threadIdx.y;

    if (bid >= NB_TILES) {
        // wte elementwise split (no transpose)
        int i = (bid - NB_TILES) * 256 + ty * 32 + tx;
        if (i < V_ * E_ / 4) {
            float4 v = reinterpret_cast<const float4*>(wte)[i];
            uint32_t hp, lp;
            split2(v.x, v.y, hp, lp);
            reinterpret_cast<uint32_t*>(wh + OFF_WTE)[2 * i] = hp;
            reinterpret_cast<uint32_t*>(wl + OFF_WTE)[2 * i] = lp;
            split2(v.z, v.w, hp, lp);
            reinterpret_cast<uint32_t*>(wh + OFF_WTE)[2 * i + 1] = hp;
            reinterpret_cast<uint32_t*>(wl + OFF_WTE)[2 * i + 1] = lp;
        }
        return;
    }

    const float* w;
    __nv_bfloat16 *hi, *lo;
    int K, N, nx;
    if (bid < NB_AW) {
        w = aw; hi = wh + OFF_AW; lo = wl + OFF_AW; K = 512; N = 1536; nx = 48;
    } else if (bid < NB_AW + NB_PW) {
        bid -= NB_AW;
        w = pw; hi = wh + OFF_PW; lo = wl + OFF_PW; K = 512; N = 512; nx = 16;
    } else if (bid < NB_AW + NB_PW + NB_FW) {
        bid -= NB_AW + NB_PW;
        w = fw; hi = wh + OFF_FW; lo = wl + OFF_FW; K = 512; N = 2048; nx = 64;
    } else {
        bid -= NB_AW + NB_PW + NB_FW;
        w = fpw; hi = wh + OFF_FPW; lo = wl + OFF_FPW; K = 2048; N = 512; nx = 16;
    }
    int tiles = (K / 32) * nx;
    int z = bid / tiles, rem = bid % tiles;
    int n0 = (rem % nx) * 32, k0 = (rem / nx) * 32;
    w += (size_t)z * K * N;
    hi += (size_t)z * N * K;
    lo += (size_t)z * N * K;

    __shared__ float t[32][33];
#pragma unroll
    for (int j = 0; j < 4; j++)
        t[ty + j * 8][tx] = w[(size_t)(k0 + ty + j * 8) * N + n0 + tx];
    __syncthreads();
#pragma unroll
    for (int j = 0; j < 4; j++) {
        int n = n0 + ty + j * 8, k = k0 + tx;
        float v = t[tx][ty + j * 8];
        __nv_bfloat16 h = __float2bfloat16(v);
        hi[(size_t)n * K + k] = h;
        lo[(size_t)n * K + k] = __float2bfloat16(v - __bfloat162float(h));
    }
}

// ---------------- embedding ----------------
__global__ void embed_kernel(const int* __restrict__ idx,
                             const float* __restrict__ wte,
                             const float* __restrict__ wpe,
                             float* __restrict__ out) {
    int t = blockIdx.x;
    int pos = t % T_;
    int id = idx[t];
    float4 a = reinterpret_cast<const float4*>(wte + (long long)id * E_)[threadIdx.x];
    float4 b = reinterpret_cast<const float4*>(wpe + (long long)pos * E_)[threadIdx.x];
    float4 o;
    o.x = a.x + b.x; o.y = a.y + b.y; o.z = a.z + b.z; o.w = a.w + b.w;
    reinterpret_cast<float4*>(out + (long long)t * E_)[threadIdx.x] = o;
}

// ---------------- LayerNorm -> split bf16 ----------------
__global__ void ln_split(const float* __restrict__ x, const float* __restrict__ w,
                         __nv_bfloat16* __restrict__ oh, __nv_bfloat16* __restrict__ ol) {
    int row = blockIdx.x;
    float4 v = reinterpret_cast<const float4*>(x + (long long)row * E_)[threadIdx.x];
    float s = v.x + v.y + v.z + v.w;
    float ss = v.x * v.x + v.y * v.y + v.z * v.z + v.w * v.w;
    __shared__ float sh[8];
#pragma unroll
    for (int o = 16; o > 0; o >>= 1) {
        s += __shfl_down_sync(0xffffffffu, s, o);
        ss += __shfl_down_sync(0xffffffffu, ss, o);
    }
    int wid = threadIdx.x >> 5, lane = threadIdx.x & 31;
    if (lane == 0) { sh[wid] = s; sh[4 + wid] = ss; }
    __syncthreads();
    if (threadIdx.x == 0) {
        float ts = sh[0] + sh[1] + sh[2] + sh[3];
        float tss = sh[4] + sh[5] + sh[6] + sh[7];
        float m = ts * (1.f / E_);
        float var = tss * (1.f / E_) - m * m;
        sh[0] = m;
        sh[1] = rsqrtf(var + 1e-5f);
    }
    __syncthreads();
    float m = sh[0], r = sh[1];
    float4 wv = reinterpret_cast<const float4*>(w)[threadIdx.x];
    float o0 = (v.x - m) * r * wv.x;
    float o1 = (v.y - m) * r * wv.y;
    float o2 = (v.z - m) * r * wv.z;
    float o3 = (v.w - m) * r * wv.w;
    size_t base = (size_t)row * E_ + threadIdx.x * 4;
    uint32_t hp, lp;
    split2(o0, o1, hp, lp);
    *reinterpret_cast<uint32_t*>(oh + base) = hp;
    *reinterpret_cast<uint32_t*>(ol + base) = lp;
    split2(o2, o3, hp, lp);
    *reinterpret_cast<uint32_t*>(oh + base + 2) = hp;
    *reinterpret_cast<uint32_t*>(ol + base + 2) = lp;
}

// =================================================================
//                          host pipeline
// =================================================================
extern "C" void kernel_launch(void* const* d_in, const int* in_sizes, int n_in,
                              void* d_out, int out_size) {
    (void)in_sizes; (void)n_in; (void)out_size;
    const int* idx = (const int*)d_in[0];
    const float* wte = (const float*)d_in[1];
    const float* wpe = (const float*)d_in[2];
    const float* aw = (const float*)d_in[3];
    const float* pw = (const float*)d_in[4];
    const float* fw = (const float*)d_in[5];
    const float* fpw = (const float*)d_in[6];
    const float* l1 = (const float*)d_in[7];
    const float* l2 = (const float*)d_in[8];
    const float* lnf = (const float*)d_in[9];
    float* out = (float*)d_out;

    float* gx;
    __nv_bfloat16 *glnh, *glnl, *gqh, *gql, *gkh, *gkl, *gvh, *gvl, *gyh, *gyl, *gh2h, *gh2l, *gwh, *gwl;
    cudaGetSymbolAddress((void**)&gx, g_x);
    cudaGetSymbolAddress((void**)&glnh, g_lnh);
    cudaGetSymbolAddress((void**)&glnl, g_lnl);
    cudaGetSymbolAddress((void**)&gqh, g_qh);
    cudaGetSymbolAddress((void**)&gql, g_ql);
    cudaGetSymbolAddress((void**)&gkh, g_kh);
    cudaGetSymbolAddress((void**)&gkl, g_kl);
    cudaGetSymbolAddress((void**)&gvh, g_vh);
    cudaGetSymbolAddress((void**)&gvl, g_vl);
    cudaGetSymbolAddress((void**)&gyh, g_yh);
    cudaGetSymbolAddress((void**)&gyl, g_yl);
    cudaGetSymbolAddress((void**)&gh2h, g_h2h);
    cudaGetSymbolAddress((void**)&gh2l, g_h2l);
    cudaGetSymbolAddress((void**)&gwh, g_wh);
    cudaGetSymbolAddress((void**)&gwl, g_wl);

    cudaFuncSetAttribute(gemm_mma<0>, cudaFuncAttributeMaxDynamicSharedMemorySize, SMEM_MMA_BYTES);
    cudaFuncSetAttribute(gemm_mma<2>, cudaFuncAttributeMaxDynamicSharedMemorySize, SMEM_MMA_BYTES);
    cudaFuncSetAttribute(gemm_mma<3>, cudaFuncAttributeMaxDynamicSharedMemorySize, SMEM_MMA_BYTES);
    cudaFuncSetAttribute(gemm_mma<4>, cudaFuncAttributeMaxDynamicSharedMemorySize, SMEM_MMA_BYTES);
    cudaFuncSetAttribute(flash_attn, cudaFuncAttributeMaxDynamicSharedMemorySize, AT_SMEM);

    // single fused weight-conversion launch
    split_weights<<<NB_ALL, dim3(32, 8)>>>(aw, pw, fw, fpw, wte, gwh, gwl);

    embed_kernel<<<B_ * T_, 128>>>(idx, wte, wpe, gx);

    for (int l = 0; l < L_; l++) {
        ln_split<<<B_ * T_, 128>>>(gx, l1 + (long long)l * E_, glnh, glnl);
        gemm_mma<3><<<dim3(12, 32), 256, SMEM_MMA_BYTES>>>(
            glnh, glnl, gwh + OFF_AW + (size_t)l * 3 * E_ * E_, gwl + OFF_AW + (size_t)l * 3 * E_ * E_,
            nullptr, gx, 1536, 512, 1536);
        flash_attn<<<dim3(8, 32), 128, AT_SMEM>>>(gqh, gql, gkh, gkl, gvh, gvl, gyh, gyl);
        gemm_mma<2><<<dim3(4, 32), 256, SMEM_MMA_BYTES>>>(
            gyh, gyl, gwh + OFF_PW + (size_t)l * E_ * E_, gwl + OFF_PW + (size_t)l * E_ * E_,
            gx, gx, 512, 512, 512);
        ln_split<<<B_ * T_, 128>>>(gx, l2 + (long long)l * E_, glnh, glnl);
        gemm_mma<4><<<dim3(16, 32), 256, SMEM_MMA_BYTES>>>(
            glnh, glnl, gwh + OFF_FW + (size_t)l * 4 * E_ * E_, gwl + OFF_FW + (size_t)l * 4 * E_ * E_,
            nullptr, gx, 2048, 512, 2048);
        gemm_mma<2><<<dim3(4, 32), 256, SMEM_MMA_BYTES>>>(
            gh2h, gh2l, gwh + OFF_FPW + (size_t)l * E_ * 4 * E_, gwl + OFF_FPW + (size_t)l * E_ * 4 * E_,
            gx, gx, 512, 2048, 512);
    }

    ln_split<<<B_ * T_, 128>>>(gx, lnf, glnh, glnl);
    gemm_mma<0><<<dim3(3, 32), 256, SMEM_MMA_BYTES>>>(
        glnh, glnl, gwh + OFF_WTE, gwl + OFF_WTE,
        nullptr, out, V_, 512, V_);
}

// round 16
// speedup vs baseline: 1.0172x; 1.0172x over previous
#include <cuda_runtime.h>
#include <cuda_bf16.h>
#include <math.h>
#include <stdint.h>

#define V_ 371
#define E_ 512
#define H_ 8
#define L_ 8
#define B_ 4
#define T_ 1024
#define D_ 64

// ---------------- scratch (static device globals; no allocation) ----------------
__device__ __align__(256) float g_x[B_ * T_ * E_];
__device__ __align__(256) __nv_bfloat16 g_lnh[B_ * T_ * E_];
__device__ __align__(256) __nv_bfloat16 g_lnl[B_ * T_ * E_];
__device__ __align__(256) __nv_bfloat16 g_qh[B_ * H_ * T_ * D_];
__device__ __align__(256) __nv_bfloat16 g_ql[B_ * H_ * T_ * D_];
__device__ __align__(256) __nv_bfloat16 g_kh[B_ * H_ * T_ * D_];
__device__ __align__(256) __nv_bfloat16 g_kl[B_ * H_ * T_ * D_];
__device__ __align__(256) __nv_bfloat16 g_vh[B_ * H_ * T_ * D_];   // v row-major [bh,t,d]
__device__ __align__(256) __nv_bfloat16 g_vl[B_ * H_ * T_ * D_];
__device__ __align__(256) __nv_bfloat16 g_yh[B_ * T_ * E_];
__device__ __align__(256) __nv_bfloat16 g_yl[B_ * T_ * E_];
__device__ __align__(256) __nv_bfloat16 g_h2h[B_ * T_ * 4 * E_];
__device__ __align__(256) __nv_bfloat16 g_h2l[B_ * T_ * 4 * E_];

#define OFF_AW 0
#define SZ_AW (L_ * 3 * E_ * E_)
#define OFF_PW (OFF_AW + SZ_AW)
#define SZ_PW (L_ * E_ * E_)
#define OFF_FW (OFF_PW + SZ_PW)
#define SZ_FW (L_ * 4 * E_ * E_)
#define OFF_FPW (OFF_FW + SZ_FW)
#define SZ_FPW (L_ * E_ * 4 * E_)
#define OFF_WTE (OFF_FPW + SZ_FPW)
#define SZ_WTE_PAD (384 * E_)
#define SZ_WALL (OFF_WTE + SZ_WTE_PAD)
__device__ __align__(256) __nv_bfloat16 g_wh[SZ_WALL];
__device__ __align__(256) __nv_bfloat16 g_wl[SZ_WALL];

// =================================================================
//                        small helpers
// =================================================================
__device__ __forceinline__ uint32_t smem_u32(const void* p) {
    uint32_t a;
    asm("{ .reg .u64 t; cvta.to.shared.u64 t, %1; cvt.u32.u64 %0, t; }" : "=r"(a) : "l"(p));
    return a;
}
__device__ __forceinline__ void cpa16(void* sdst, const void* gsrc) {
    uint32_t s = smem_u32(sdst);
    asm volatile("cp.async.cg.shared.global [%0], [%1], 16;" :: "r"(s), "l"(gsrc));
}
__device__ __forceinline__ void mma_bf16(float* c, const uint32_t* a, const uint32_t* b) {
    asm volatile(
        "mma.sync.aligned.m16n8k16.row.col.f32.bf16.bf16.f32 "
        "{%0,%1,%2,%3}, {%4,%5,%6,%7}, {%8,%9}, {%0,%1,%2,%3};"
        : "+f"(c[0]), "+f"(c[1]), "+f"(c[2]), "+f"(c[3])
        : "r"(a[0]), "r"(a[1]), "r"(a[2]), "r"(a[3]), "r"(b[0]), "r"(b[1]));
}
__device__ __forceinline__ void ldsm_x4(uint32_t* r, uint32_t addr) {
    asm volatile("ldmatrix.sync.aligned.m8n8.x4.shared.b16 {%0,%1,%2,%3}, [%4];"
                 : "=r"(r[0]), "=r"(r[1]), "=r"(r[2]), "=r"(r[3]) : "r"(addr));
}
__device__ __forceinline__ void ldsm_x4_t(uint32_t* r, uint32_t addr) {
    asm volatile("ldmatrix.sync.aligned.m8n8.x4.trans.shared.b16 {%0,%1,%2,%3}, [%4];"
                 : "=r"(r[0]), "=r"(r[1]), "=r"(r[2]), "=r"(r[3]) : "r"(addr));
}
__device__ __forceinline__ void split2(float x0, float x1, uint32_t& hp, uint32_t& lp) {
    __nv_bfloat16 h0 = __float2bfloat16(x0), h1 = __float2bfloat16(x1);
    __nv_bfloat162 hh(h0, h1);
    hp = *reinterpret_cast<uint32_t*>(&hh);
    __nv_bfloat16 l0 = __float2bfloat16(x0 - __bfloat162float(h0));
    __nv_bfloat16 l1 = __float2bfloat16(x1 - __bfloat162float(h1));
    __nv_bfloat162 ll(l0, l1);
    lp = *reinterpret_cast<uint32_t*>(&ll);
}

// =================================================================
//   HMMA split-bf16 GEMM 128x128 — single barrier per K-chunk
// =================================================================
#define SROW 40
#define STILE (128 * SROW)
#define SMEM_MMA_BYTES (2 * 4 * STILE * 2)

template <int EPI>
__global__ void __launch_bounds__(256, 2)
gemm_mma(const __nv_bfloat16* __restrict__ Ah, const __nv_bfloat16* __restrict__ Al,
         const __nv_bfloat16* __restrict__ Bh, const __nv_bfloat16* __restrict__ Bl,
         const float* __restrict__ Add, float* __restrict__ C,
         int N, int K, int ldc) {
    extern __shared__ __nv_bfloat16 smh[];
    int tid = threadIdx.x;
    int wid = tid >> 5, lane = tid & 31;
    int wm = wid >> 1, wn = wid & 1;
    int lr = lane >> 2, lc = lane & 3;

    int m0 = blockIdx.y * 128;
    int n0 = blockIdx.x * 128;

    const __nv_bfloat16* srcs[4] = {
        Ah + (size_t)m0 * K, Al + (size_t)m0 * K,
        Bh + (size_t)n0 * K, Bl + (size_t)n0 * K};

    int lrow = tid >> 1;
    int q0 = (tid & 1) * 2;
    int nch = K >> 5;

    uint32_t sbu = smem_u32(smh);
    uint32_t a_lane = (uint32_t)((lane & 15) * SROW + (lane >> 4) * 8);
    uint32_t b_lane = (uint32_t)((((lane >> 4) << 3) + (lane & 7)) * SROW + ((lane >> 3) & 1) * 8);

    {
#pragma unroll
        for (int t = 0; t < 4; t++) {
            const __nv_bfloat16* sp = srcs[t] + (size_t)lrow * K;
            __nv_bfloat16* dp = smh + t * STILE + lrow * SROW;
            cpa16(dp + q0 * 8, sp + q0 * 8);
            cpa16(dp + (q0 + 1) * 8, sp + (q0 + 1) * 8);
        }
        asm volatile("cp.async.commit_group;");
    }

    float acc[2][8][4];
#pragma unroll
    for (int i = 0; i < 2; i++)
#pragma unroll
        for (int j = 0; j < 8; j++)
#pragma unroll
            for (int r = 0; r < 4; r++) acc[i][j][r] = 0.f;

    for (int c = 0; c < nch; c++) {
        // wait for chunk c's data, one barrier; then prefetch c+1 (safe:
        // the barrier proves all warps finished reading buffer (c+1)&1
        // during iteration c-1).
        asm volatile("cp.async.wait_group 0;");
        __syncthreads();
        if (c + 1 < nch) {
            int k0 = (c + 1) << 5;
            __nv_bfloat16* sb = smh + ((c + 1) & 1) * 4 * STILE;
#pragma unroll
            for (int t = 0; t < 4; t++) {
                const __nv_bfloat16* sp = srcs[t] + (size_t)lrow * K + k0;
                __nv_bfloat16* dp = sb + t * STILE + lrow * SROW;
                cpa16(dp + q0 * 8, sp + q0 * 8);
                cpa16(dp + (q0 + 1) * 8, sp + (q0 + 1) * 8);
            }
            asm volatile("cp.async.commit_group;");
        }

        uint32_t tbu = sbu + (uint32_t)((c & 1) * 4 * STILE) * 2u;
        uint32_t pAh = tbu;
        uint32_t pAl = tbu + STILE * 2u;
        uint32_t pBh = tbu + 2u * STILE * 2u;
        uint32_t pBl = tbu + 3u * STILE * 2u;

#pragma unroll
        for (int ks = 0; ks < 2; ks++) {
            uint32_t kso = (uint32_t)(ks * 16) * 2u;
            uint32_t ah[2][4], al[2][4], bh[8][2], bl[8][2];
#pragma unroll
            for (int i = 0; i < 2; i++) {
                uint32_t off = (uint32_t)((wm * 32 + i * 16) * SROW) * 2u + a_lane * 2u + kso;
                ldsm_x4(ah[i], pAh + off);
                ldsm_x4(al[i], pAl + off);
            }
#pragma unroll
            for (int jp = 0; jp < 4; jp++) {
                uint32_t off = (uint32_t)((wn * 64 + jp * 16) * SROW) * 2u + b_lane * 2u + kso;
                uint32_t q[4];
                ldsm_x4(q, pBh + off);
                bh[2 * jp][0] = q[0]; bh[2 * jp][1] = q[1];
                bh[2 * jp + 1][0] = q[2]; bh[2 * jp + 1][1] = q[3];
                ldsm_x4(q, pBl + off);
                bl[2 * jp][0] = q[0]; bl[2 * jp][1] = q[1];
                bl[2 * jp + 1][0] = q[2]; bl[2 * jp + 1][1] = q[3];
            }
#pragma unroll
            for (int i = 0; i < 2; i++)
#pragma unroll
                for (int j = 0; j < 8; j++) mma_bf16(acc[i][j], ah[i], bh[j]);
#pragma unroll
            for (int i = 0; i < 2; i++)
#pragma unroll
                for (int j = 0; j < 8; j++) mma_bf16(acc[i][j], ah[i], bl[j]);
#pragma unroll
            for (int i = 0; i < 2; i++)
#pragma unroll
                for (int j = 0; j < 8; j++) mma_bf16(acc[i][j], al[i], bh[j]);
        }
    }

#pragma unroll
    for (int i = 0; i < 2; i++) {
#pragma unroll
        for (int half = 0; half < 2; half++) {
            int r = m0 + wm * 32 + i * 16 + lr + half * 8;
#pragma unroll
            for (int j = 0; j < 8; j++) {
                int col = n0 + wn * 64 + j * 8 + lc * 2;
                float v0 = acc[i][j][half * 2 + 0];
                float v1 = acc[i][j][half * 2 + 1];
                if (EPI == 0) {
                    float* crow = C + (size_t)r * ldc;
                    if (col < N) crow[col] = v0;
                    if (col + 1 < N) crow[col + 1] = v1;
                } else if (EPI == 2) {
                    const float* arow = Add + (size_t)r * ldc + col;
                    float2 a = *reinterpret_cast<const float2*>(arow);
                    *reinterpret_cast<float2*>(C + (size_t)r * ldc + col) =
                        make_float2(v0 + a.x, v1 + a.y);
                } else if (EPI == 3) {
                    int b = r >> 10, t = r & 1023;
                    int seg = col >> 9, cc = col & 511;
                    int hh = cc >> 6, d = cc & 63;
                    size_t bht = (((size_t)(b * 8 + hh)) << 10) + t;
                    uint32_t hp, lp;
                    if (seg == 0) {
                        v0 *= 0.125f; v1 *= 0.125f;
                        split2(v0, v1, hp, lp);
                        *reinterpret_cast<uint32_t*>(g_qh + bht * 64 + d) = hp;
                        *reinterpret_cast<uint32_t*>(g_ql + bht * 64 + d) = lp;
                    } else if (seg == 1) {
                        split2(v0, v1, hp, lp);
                        *reinterpret_cast<uint32_t*>(g_kh + bht * 64 + d) = hp;
                        *reinterpret_cast<uint32_t*>(g_kl + bht * 64 + d) = lp;
                    } else {
                        split2(v0, v1, hp, lp);
                        *reinterpret_cast<uint32_t*>(g_vh + bht * 64 + d) = hp;
                        *reinterpret_cast<uint32_t*>(g_vl + bht * 64 + d) = lp;
                    }
                } else if (EPI == 4) {
                    v0 = 0.5f * v0 * (1.f + erff(v0 * 0.70710678118654752440f));
                    v1 = 0.5f * v1 * (1.f + erff(v1 * 0.70710678118654752440f));
                    uint32_t hp, lp; split2(v0, v1, hp, lp);
                    size_t off = (size_t)r * 2048 + col;
                    *reinterpret_cast<uint32_t*>(g_h2h + off) = hp;
                    *reinterpret_cast<uint32_t*>(g_h2l + off) = lp;
                }
            }
        }
    }
}

// =================================================================
//    Fused flash attention — single barrier per key block
// =================================================================
#define AT_SMEM 73728

__device__ __forceinline__ void at_load_kv(
    __nv_bfloat16* sm, int tid,
    const __nv_bfloat16* kh, const __nv_bfloat16* kl,
    const __nv_bfloat16* vh, const __nv_bfloat16* vl,
    size_t qkoff, int kb, int bsel) {
    int row = tid >> 1;
    int q0 = (tid & 1) * 4;
    __nv_bfloat16* base = sm + bsel * 18432;
    const __nv_bfloat16* gkh = kh + qkoff + (size_t)(kb * 64 + row) * 64;
    const __nv_bfloat16* gkl = kl + qkoff + (size_t)(kb * 64 + row) * 64;
    const __nv_bfloat16* gvh = vh + qkoff + (size_t)(kb * 64 + row) * 64;
    const __nv_bfloat16* gvl = vl + qkoff + (size_t)(kb * 64 + row) * 64;
#pragma unroll
    for (int c = 0; c < 4; c++) {
        cpa16(base + row * 72 + (q0 + c) * 8, gkh + (q0 + c) * 8);
        cpa16(base + 4608 + row * 72 + (q0 + c) * 8, gkl + (q0 + c) * 8);
        cpa16(base + 9216 + row * 72 + (q0 + c) * 8, gvh + (q0 + c) * 8);
        cpa16(base + 13824 + row * 72 + (q0 + c) * 8, gvl + (q0 + c) * 8);
    }
}

__global__ void __launch_bounds__(128)
flash_attn(const __nv_bfloat16* __restrict__ qh, const __nv_bfloat16* __restrict__ ql,
           const __nv_bfloat16* __restrict__ kh, const __nv_bfloat16* __restrict__ kl,
           const __nv_bfloat16* __restrict__ vh, const __nv_bfloat16* __restrict__ vl,
           __nv_bfloat16* __restrict__ yh, __nv_bfloat16* __restrict__ yl) {
    extern __shared__ __nv_bfloat16 sm[];
    int tid = threadIdx.x, w = tid >> 5, lane = tid & 31;
    int lr = lane >> 2, lc = lane & 3;
    int qb = 7 - blockIdx.x;
    int bh = blockIdx.y;
    const size_t qkoff = (size_t)bh << 16;

    uint32_t smu = smem_u32(sm);
    uint32_t b_lane72 = (uint32_t)((((lane >> 4) << 3) + (lane & 7)) * 72 + ((lane >> 3) & 1) * 8);
    uint32_t a_lane72 = (uint32_t)((lane & 15) * 72 + (lane >> 4) * 8);

    {
        const __nv_bfloat16* gq = qh + qkoff + (size_t)(qb * 128 + tid) * 64;
        const __nv_bfloat16* gq2 = ql + qkoff + (size_t)(qb * 128 + tid) * 64;
        __nv_bfloat16* dh = sm + tid * 72;
        __nv_bfloat16* dl = sm + 9216 + tid * 72;
#pragma unroll
        for (int q = 0; q < 8; q++) { cpa16(dh + q * 8, gq + q * 8); cpa16(dl + q * 8, gq2 + q * 8); }
        asm volatile("cp.async.commit_group;");
        asm volatile("cp.async.wait_group 0;");
        __syncthreads();
    }
    uint32_t qfh[2][4][4], qfl[2][4][4];
#pragma unroll
    for (int mt = 0; mt < 2; mt++)
#pragma unroll
        for (int kk = 0; kk < 4; kk++) {
            int r = w * 32 + mt * 16 + lr;
            const __nv_bfloat16* p = sm + r * 72 + kk * 16 + lc * 2;
            qfh[mt][kk][0] = *(const uint32_t*)p;
            qfh[mt][kk][1] = *(const uint32_t*)(p + 8 * 72);
            qfh[mt][kk][2] = *(const uint32_t*)(p + 8);
            qfh[mt][kk][3] = *(const uint32_t*)(p + 8 * 72 + 8);
            const __nv_bfloat16* p2 = p + 9216;
            qfl[mt][kk][0] = *(const uint32_t*)p2;
            qfl[mt][kk][1] = *(const uint32_t*)(p2 + 8 * 72);
            qfl[mt][kk][2] = *(const uint32_t*)(p2 + 8);
            qfl[mt][kk][3] = *(const uint32_t*)(p2 + 8 * 72 + 8);
        }
    __syncthreads();

    float m_[4], l_[4], o[2][8][4];
#pragma unroll
    for (int s = 0; s < 4; s++) { m_[s] = -1e30f; l_[s] = 0.f; }
#pragma unroll
    for (int i = 0; i < 2; i++)
#pragma unroll
        for (int j = 0; j < 8; j++)
#pragma unroll
            for (int r = 0; r < 4; r++) o[i][j][r] = 0.f;

    int nkb = 2 * qb + 2;
    at_load_kv(sm, tid, kh, kl, vh, vl, qkoff, 0, 1);
    asm volatile("cp.async.commit_group;");

    for (int kb = 0; kb < nkb; kb++) {
        // one barrier per block: wait for kb's data, then prefetch kb+1
        asm volatile("cp.async.wait_group 0;");
        __syncthreads();
        if (kb + 1 < nkb) {
            at_load_kv(sm, tid, kh, kl, vh, vl, qkoff, kb + 1, kb & 1);
            asm volatile("cp.async.commit_group;");
        }

        bool active = !(kb == 2 * qb + 1 && w < 2);
        bool need_mask = (kb == 2 * qb && w < 2) || (kb == 2 * qb + 1 && w >= 2);

        if (active) {
            uint32_t bb = smu + (uint32_t)(((kb + 1) & 1) * 18432) * 2u;
            uint32_t pKh = bb;
            uint32_t pKl = bb + 4608 * 2u;
            uint32_t pVh = bb + 9216 * 2u;
            uint32_t pVl = bb + 13824 * 2u;

            float s[2][8][4];
#pragma unroll
            for (int i = 0; i < 2; i++)
#pragma unroll
                for (int j = 0; j < 8; j++)
#pragma unroll
                    for (int r = 0; r < 4; r++) s[i][j][r] = 0.f;

#pragma unroll
            for (int kk = 0; kk < 4; kk++) {
                uint32_t kso = (uint32_t)(kk * 16) * 2u;
                uint32_t bh_[8][2], bl_[8][2];
#pragma unroll
                for (int jp = 0; jp < 4; jp++) {
                    uint32_t off = (uint32_t)(jp * 16 * 72) * 2u + b_lane72 * 2u + kso;
                    uint32_t q[4];
                    ldsm_x4(q, pKh + off);
                    bh_[2 * jp][0] = q[0]; bh_[2 * jp][1] = q[1];
                    bh_[2 * jp + 1][0] = q[2]; bh_[2 * jp + 1][1] = q[3];
                    ldsm_x4(q, pKl + off);
                    bl_[2 * jp][0] = q[0]; bl_[2 * jp][1] = q[1];
                    bl_[2 * jp + 1][0] = q[2]; bl_[2 * jp + 1][1] = q[3];
                }
#pragma unroll
                for (int jn = 0; jn < 8; jn++)
#pragma unroll
                    for (int mt = 0; mt < 2; mt++) {
                        mma_bf16(s[mt][jn], qfh[mt][kk], bh_[jn]);
                        mma_bf16(s[mt][jn], qfh[mt][kk], bl_[jn]);
                        mma_bf16(s[mt][jn], qfl[mt][kk], bh_[jn]);
                    }
            }

            if (need_mask) {
                int rowbase = qb * 128 + w * 32;
                int colbase = kb * 64;
#pragma unroll
                for (int mt = 0; mt < 2; mt++)
#pragma unroll
                    for (int jn = 0; jn < 8; jn++)
#pragma unroll
                        for (int idx = 0; idx < 4; idx++) {
                            int row = rowbase + mt * 16 + lr + ((idx >> 1) << 3);
                            int col = colbase + jn * 8 + lc * 2 + (idx & 1);
                            if (col > row) s[mt][jn][idx] = -1e30f;
                        }
            }

            float scl[4];
#pragma unroll
            for (int sl = 0; sl < 4; sl++) {
                int mt = sl >> 1, h = sl & 1;
                float cm = -1e30f;
#pragma unroll
                for (int jn = 0; jn < 8; jn++)
                    cm = fmaxf(cm, fmaxf(s[mt][jn][h * 2], s[mt][jn][h * 2 + 1]));
                cm = fmaxf(cm, __shfl_xor_sync(0xffffffffu, cm, 1));
                cm = fmaxf(cm, __shfl_xor_sync(0xffffffffu, cm, 2));
                float mnew = fmaxf(m_[sl], cm);
                scl[sl] = __expf(m_[sl] - mnew);
                m_[sl] = mnew;
            }
            float rs[4] = {0.f, 0.f, 0.f, 0.f};
#pragma unroll
            for (int mt = 0; mt < 2; mt++)
#pragma unroll
                for (int jn = 0; jn < 8; jn++) {
                    s[mt][jn][0] = __expf(s[mt][jn][0] - m_[mt * 2]);
                    s[mt][jn][1] = __expf(s[mt][jn][1] - m_[mt * 2]);
                    s[mt][jn][2] = __expf(s[mt][jn][2] - m_[mt * 2 + 1]);
                    s[mt][jn][3] = __expf(s[mt][jn][3] - m_[mt * 2 + 1]);
                    rs[mt * 2] += s[mt][jn][0] + s[mt][jn][1];
                    rs[mt * 2 + 1] += s[mt][jn][2] + s[mt][jn][3];
                }
#pragma unroll
            for (int sl = 0; sl < 4; sl++) {
                rs[sl] += __shfl_xor_sync(0xffffffffu, rs[sl], 1);
                rs[sl] += __shfl_xor_sync(0xffffffffu, rs[sl], 2);
                l_[sl] = l_[sl] * scl[sl] + rs[sl];
            }
#pragma unroll
            for (int mt = 0; mt < 2; mt++)
#pragma unroll
                for (int jn = 0; jn < 8; jn++) {
                    o[mt][jn][0] *= scl[mt * 2];
                    o[mt][jn][1] *= scl[mt * 2];
                    o[mt][jn][2] *= scl[mt * 2 + 1];
                    o[mt][jn][3] *= scl[mt * 2 + 1];
                }

#pragma unroll
            for (int kk = 0; kk < 4; kk++) {
                uint32_t pah[2][4], pal[2][4];
#pragma unroll
                for (int mt = 0; mt < 2; mt++) {
                    split2(s[mt][2 * kk][0], s[mt][2 * kk][1], pah[mt][0], pal[mt][0]);
                    split2(s[mt][2 * kk][2], s[mt][2 * kk][3], pah[mt][1], pal[mt][1]);
                    split2(s[mt][2 * kk + 1][0], s[mt][2 * kk + 1][1], pah[mt][2], pal[mt][2]);
                    split2(s[mt][2 * kk + 1][2], s[mt][2 * kk + 1][3], pah[mt][3], pal[mt][3]);
                }
                uint32_t vh_[8][2], vl_[8][2];
#pragma unroll
                for (int jp = 0; jp < 4; jp++) {
                    uint32_t off = (uint32_t)(kk * 16 * 72 + jp * 16) * 2u + a_lane72 * 2u;
                    uint32_t q[4];
                    ldsm_x4_t(q, pVh + off);
                    vh_[2 * jp][0] = q[0]; vh_[2 * jp][1] = q[1];
                    vh_[2 * jp + 1][0] = q[2]; vh_[2 * jp + 1][1] = q[3];
                    ldsm_x4_t(q, pVl + off);
                    vl_[2 * jp][0] = q[0]; vl_[2 * jp][1] = q[1];
                    vl_[2 * jp + 1][0] = q[2]; vl_[2 * jp + 1][1] = q[3];
                }
#pragma unroll
                for (int jn = 0; jn < 8; jn++)
#pragma unroll
                    for (int mt = 0; mt < 2; mt++) {
                        mma_bf16(o[mt][jn], pah[mt], vh_[jn]);
                        mma_bf16(o[mt][jn], pah[mt], vl_[jn]);
                        mma_bf16(o[mt][jn], pal[mt], vh_[jn]);
                    }
            }
        }
    }

    int b = bh >> 3, hhd = bh & 7;
#pragma unroll
    for (int mt = 0; mt < 2; mt++)
#pragma unroll
        for (int h = 0; h < 2; h++) {
            int t = qb * 128 + w * 32 + mt * 16 + lr + h * 8;
            size_t row = (size_t)(b * 1024 + t) * 512 + hhd * 64;
            float inv = 1.f / l_[mt * 2 + h];
#pragma unroll
            for (int jn = 0; jn < 8; jn++) {
                int col = jn * 8 + lc * 2;
                float x0 = o[mt][jn][h * 2] * inv;
                float x1 = o[mt][jn][h * 2 + 1] * inv;
                uint32_t hp, lp;
                split2(x0, x1, hp, lp);
                *reinterpret_cast<uint32_t*>(yh + row + col) = hp;
                *reinterpret_cast<uint32_t*>(yl + row + col) = lp;
            }
        }
}

// ---------------- fp32 -> bf16 hi/lo split (weights/wte only) ----------------
__global__ void split_act(const float4* __restrict__ x, __nv_bfloat16* __restrict__ hi,
                          __nv_bfloat16* __restrict__ lo, int n4) {
    int i = blockIdx.x * blockDim.x + threadIdx.x;
    if (i >= n4) return;
    float4 v = x[i];
    uint32_t hp, lp;
    split2(v.x, v.y, hp, lp);
    reinterpret_cast<uint32_t*>(hi)[2 * i] = hp;
    reinterpret_cast<uint32_t*>(lo)[2 * i] = lp;
    split2(v.z, v.w, hp, lp);
    reinterpret_cast<uint32_t*>(hi)[2 * i + 1] = hp;
    reinterpret_cast<uint32_t*>(lo)[2 * i + 1] = lp;
}

// ---------------- weight split + transpose: W[K,N] fp32 -> hi/lo [N,K] bf16 ----------------
__global__ void split_wT(const float* __restrict__ w, __nv_bfloat16* __restrict__ hi,
                         __nv_bfloat16* __restrict__ lo, int K, int N) {
    __shared__ float t[32][33];
    int z = blockIdx.z;
    w += (size_t)z * K * N;
    hi += (size_t)z * N * K;
    lo += (size_t)z * N * K;
    int n0 = blockIdx.x * 32, k0 = blockIdx.y * 32;
    int tx = threadIdx.x, ty = threadIdx.y;
#pragma unroll
    for (int j = 0; j < 4; j++)
        t[ty + j * 8][tx] = w[(size_t)(k0 + ty + j * 8) * N + n0 + tx];
    __syncthreads();
#pragma unroll
    for (int j = 0; j < 4; j++) {
        int n = n0 + ty + j * 8, k = k0 + tx;
        float v = t[tx][ty + j * 8];
        __nv_bfloat16 h = __float2bfloat16(v);
        hi[(size_t)n * K + k] = h;
        lo[(size_t)n * K + k] = __float2bfloat16(v - __bfloat162float(h));
    }
}

// ---------------- embedding ----------------
__global__ void embed_kernel(const int* __restrict__ idx,
                             const float* __restrict__ wte,
                             const float* __restrict__ wpe,
                             float* __restrict__ out) {
    int t = blockIdx.x;
    int pos = t % T_;
    int id = idx[t];
    float4 a = reinterpret_cast<const float4*>(wte + (long long)id * E_)[threadIdx.x];
    float4 b = reinterpret_cast<const float4*>(wpe + (long long)pos * E_)[threadIdx.x];
    float4 o;
    o.x = a.x + b.x; o.y = a.y + b.y; o.z = a.z + b.z; o.w = a.w + b.w;
    reinterpret_cast<float4*>(out + (long long)t * E_)[threadIdx.x] = o;
}

// ---------------- LayerNorm -> split bf16 ----------------
__global__ void ln_split(const float* __restrict__ x, const float* __restrict__ w,
                         __nv_bfloat16* __restrict__ oh, __nv_bfloat16* __restrict__ ol) {
    int row = blockIdx.x;
    float4 v = reinterpret_cast<const float4*>(x + (long long)row * E_)[threadIdx.x];
    float s = v.x + v.y + v.z + v.w;
    float ss = v.x * v.x + v.y * v.y + v.z * v.z + v.w * v.w;
    __shared__ float sh[8];
#pragma unroll
    for (int o = 16; o > 0; o >>= 1) {
        s += __shfl_down_sync(0xffffffffu, s, o);
        ss += __shfl_down_sync(0xffffffffu, ss, o);
    }
    int wid = threadIdx.x >> 5, lane = threadIdx.x & 31;
    if (lane == 0) { sh[wid] = s; sh[4 + wid] = ss; }
    __syncthreads();
    if (threadIdx.x == 0) {
        float ts = sh[0] + sh[1] + sh[2] + sh[3];
        float tss = sh[4] + sh[5] + sh[6] + sh[7];
        float m = ts * (1.f / E_);
        float var = tss * (1.f / E_) - m * m;
        sh[0] = m;
        sh[1] = rsqrtf(var + 1e-5f);
    }
    __syncthreads();
    float m = sh[0], r = sh[1];
    float4 wv = reinterpret_cast<const float4*>(w)[threadIdx.x];
    float o0 = (v.x - m) * r * wv.x;
    float o1 = (v.y - m) * r * wv.y;
    float o2 = (v.z - m) * r * wv.z;
    float o3 = (v.w - m) * r * wv.w;
    size_t base = (size_t)row * E_ + threadIdx.x * 4;
    uint32_t hp, lp;
    split2(o0, o1, hp, lp);
    *reinterpret_cast<uint32_t*>(oh + base) = hp;
    *reinterpret_cast<uint32_t*>(ol + base) = lp;
    split2(o2, o3, hp, lp);
    *reinterpret_cast<uint32_t*>(oh + base + 2) = hp;
    *reinterpret_cast<uint32_t*>(ol + base + 2) = lp;
}

// =================================================================
//                          host pipeline
// =================================================================
extern "C" void kernel_launch(void* const* d_in, const int* in_sizes, int n_in,
                              void* d_out, int out_size) {
    (void)in_sizes; (void)n_in; (void)out_size;
    const int* idx = (const int*)d_in[0];
    const float* wte = (const float*)d_in[1];
    const float* wpe = (const float*)d_in[2];
    const float* aw = (const float*)d_in[3];
    const float* pw = (const float*)d_in[4];
    const float* fw = (const float*)d_in[5];
    const float* fpw = (const float*)d_in[6];
    const float* l1 = (const float*)d_in[7];
    const float* l2 = (const float*)d_in[8];
    const float* lnf = (const float*)d_in[9];
    float* out = (float*)d_out;

    float* gx;
    __nv_bfloat16 *glnh, *glnl, *gqh, *gql, *gkh, *gkl, *gvh, *gvl, *gyh, *gyl, *gh2h, *gh2l, *gwh, *gwl;
    cudaGetSymbolAddress((void**)&gx, g_x);
    cudaGetSymbolAddress((void**)&glnh, g_lnh);
    cudaGetSymbolAddress((void**)&glnl, g_lnl);
    cudaGetSymbolAddress((void**)&gqh, g_qh);
    cudaGetSymbolAddress((void**)&gql, g_ql);
    cudaGetSymbolAddress((void**)&gkh, g_kh);
    cudaGetSymbolAddress((void**)&gkl, g_kl);
    cudaGetSymbolAddress((void**)&gvh, g_vh);
    cudaGetSymbolAddress((void**)&gvl, g_vl);
    cudaGetSymbolAddress((void**)&gyh, g_yh);
    cudaGetSymbolAddress((void**)&gyl, g_yl);
    cudaGetSymbolAddress((void**)&gh2h, g_h2h);
    cudaGetSymbolAddress((void**)&gh2l, g_h2l);
    cudaGetSymbolAddress((void**)&gwh, g_wh);
    cudaGetSymbolAddress((void**)&gwl, g_wl);

    cudaFuncSetAttribute(gemm_mma<0>, cudaFuncAttributeMaxDynamicSharedMemorySize, SMEM_MMA_BYTES);
    cudaFuncSetAttribute(gemm_mma<2>, cudaFuncAttributeMaxDynamicSharedMemorySize, SMEM_MMA_BYTES);
    cudaFuncSetAttribute(gemm_mma<3>, cudaFuncAttributeMaxDynamicSharedMemorySize, SMEM_MMA_BYTES);
    cudaFuncSetAttribute(gemm_mma<4>, cudaFuncAttributeMaxDynamicSharedMemorySize, SMEM_MMA_BYTES);
    cudaFuncSetAttribute(flash_attn, cudaFuncAttributeMaxDynamicSharedMemorySize, AT_SMEM);

    dim3 b32(32, 8);
    split_wT<<<dim3(3 * E_ / 32, E_ / 32, L_), b32>>>(aw, gwh + OFF_AW, gwl + OFF_AW, E_, 3 * E_);
    split_wT<<<dim3(E_ / 32, E_ / 32, L_), b32>>>(pw, gwh + OFF_PW, gwl + OFF_PW, E_, E_);
    split_wT<<<dim3(4 * E_ / 32, E_ / 32, L_), b32>>>(fw, gwh + OFF_FW, gwl + OFF_FW, E_, 4 * E_);
    split_wT<<<dim3(E_ / 32, 4 * E_ / 32, L_), b32>>>(fpw, gwh + OFF_FPW, gwl + OFF_FPW, 4 * E_, E_);
    split_act<<<(V_ * E_ / 4 + 255) / 256, 256>>>((const float4*)wte, gwh + OFF_WTE, gwl + OFF_WTE, V_ * E_ / 4);

    embed_kernel<<<B_ * T_, 128>>>(idx, wte, wpe, gx);

    for (int l = 0; l < L_; l++) {
        ln_split<<<B_ * T_, 128>>>(gx, l1 + (long long)l * E_, glnh, glnl);
        gemm_mma<3><<<dim3(12, 32), 256, SMEM_MMA_BYTES>>>(
            glnh, glnl, gwh + OFF_AW + (size_t)l * 3 * E_ * E_, gwl + OFF_AW + (size_t)l * 3 * E_ * E_,
            nullptr, gx, 1536, 512, 1536);
        flash_attn<<<dim3(8, 32), 128, AT_SMEM>>>(gqh, gql, gkh, gkl, gvh, gvl, gyh, gyl);
        gemm_mma<2><<<dim3(4, 32), 256, SMEM_MMA_BYTES>>>(
            gyh, gyl, gwh + OFF_PW + (size_t)l * E_ * E_, gwl + OFF_PW + (size_t)l * E_ * E_,
            gx, gx, 512, 512, 512);
        ln_split<<<B_ * T_, 128>>>(gx, l2 + (long long)l * E_, glnh, glnl);
        gemm_mma<4><<<dim3(16, 32), 256, SMEM_MMA_BYTES>>>(
            glnh, glnl, gwh + OFF_FW + (size_t)l * 4 * E_ * E_, gwl + OFF_FW + (size_t)l * 4 * E_ * E_,
            nullptr, gx, 2048, 512, 2048);
        gemm_mma<2><<<dim3(4, 32), 256, SMEM_MMA_BYTES>>>(
            gh2h, gh2l, gwh + OFF_FPW + (size_t)l * E_ * 4 * E_, gwl + OFF_FPW + (size_t)l * E_ * 4 * E_,
            gx, gx, 512, 2048, 512);
    }

    ln_split<<<B_ * T_, 128>>>(gx, lnf, glnh, glnl);
    gemm_mma<0><<<dim3(3, 32), 256, SMEM_MMA_BYTES>>>(
        glnh, glnl, gwh + OFF_WTE, gwl + OFF_WTE,
        nullptr, out, V_, 512, V_);
}

// round 17
// speedup vs baseline: 1.0460x; 1.0283x over previous
#include <cuda_runtime.h>
#include <cuda_bf16.h>
#include <math.h>
#include <stdint.h>

#define V_ 371
#define E_ 512
#define H_ 8
#define L_ 8
#define B_ 4
#define T_ 1024
#define D_ 64

// ---------------- scratch (static device globals; no allocation) ----------------
__device__ __align__(256) float g_x[B_ * T_ * E_];
__device__ __align__(256) __nv_bfloat16 g_lnh[B_ * T_ * E_];
__device__ __align__(256) __nv_bfloat16 g_lnl[B_ * T_ * E_];
__device__ __align__(256) __nv_bfloat16 g_qh[B_ * H_ * T_ * D_];
__device__ __align__(256) __nv_bfloat16 g_ql[B_ * H_ * T_ * D_];
__device__ __align__(256) __nv_bfloat16 g_kh[B_ * H_ * T_ * D_];
__device__ __align__(256) __nv_bfloat16 g_kl[B_ * H_ * T_ * D_];
__device__ __align__(256) __nv_bfloat16 g_vh[B_ * H_ * T_ * D_];   // v row-major [bh,t,d]
__device__ __align__(256) __nv_bfloat16 g_vl[B_ * H_ * T_ * D_];
__device__ __align__(256) __nv_bfloat16 g_yh[B_ * T_ * E_];
__device__ __align__(256) __nv_bfloat16 g_yl[B_ * T_ * E_];
__device__ __align__(256) __nv_bfloat16 g_h2h[B_ * T_ * 4 * E_];
__device__ __align__(256) __nv_bfloat16 g_h2l[B_ * T_ * 4 * E_];

#define OFF_AW 0
#define SZ_AW (L_ * 3 * E_ * E_)
#define OFF_PW (OFF_AW + SZ_AW)
#define SZ_PW (L_ * E_ * E_)
#define OFF_FW (OFF_PW + SZ_PW)
#define SZ_FW (L_ * 4 * E_ * E_)
#define OFF_FPW (OFF_FW + SZ_FW)
#define SZ_FPW (L_ * E_ * 4 * E_)
#define OFF_WTE (OFF_FPW + SZ_FPW)
#define SZ_WTE_PAD (384 * E_)
#define SZ_WALL (OFF_WTE + SZ_WTE_PAD)
__device__ __align__(256) __nv_bfloat16 g_wh[SZ_WALL];
__device__ __align__(256) __nv_bfloat16 g_wl[SZ_WALL];

// =================================================================
//                        small helpers
// =================================================================
__device__ __forceinline__ uint32_t smem_u32(const void* p) {
    uint32_t a;
    asm("{ .reg .u64 t; cvta.to.shared.u64 t, %1; cvt.u32.u64 %0, t; }" : "=r"(a) : "l"(p));
    return a;
}
__device__ __forceinline__ void cpa16(void* sdst, const void* gsrc) {
    uint32_t s = smem_u32(sdst);
    asm volatile("cp.async.cg.shared.global [%0], [%1], 16;" :: "r"(s), "l"(gsrc));
}
__device__ __forceinline__ void mma_bf16(float* c, const uint32_t* a, const uint32_t* b) {
    asm volatile(
        "mma.sync.aligned.m16n8k16.row.col.f32.bf16.bf16.f32 "
        "{%0,%1,%2,%3}, {%4,%5,%6,%7}, {%8,%9}, {%0,%1,%2,%3};"
        : "+f"(c[0]), "+f"(c[1]), "+f"(c[2]), "+f"(c[3])
        : "r"(a[0]), "r"(a[1]), "r"(a[2]), "r"(a[3]), "r"(b[0]), "r"(b[1]));
}
__device__ __forceinline__ void ldsm_x4(uint32_t* r, uint32_t addr) {
    asm volatile("ldmatrix.sync.aligned.m8n8.x4.shared.b16 {%0,%1,%2,%3}, [%4];"
                 : "=r"(r[0]), "=r"(r[1]), "=r"(r[2]), "=r"(r[3]) : "r"(addr));
}
__device__ __forceinline__ void ldsm_x4_t(uint32_t* r, uint32_t addr) {
    asm volatile("ldmatrix.sync.aligned.m8n8.x4.trans.shared.b16 {%0,%1,%2,%3}, [%4];"
                 : "=r"(r[0]), "=r"(r[1]), "=r"(r[2]), "=r"(r[3]) : "r"(addr));
}
__device__ __forceinline__ void split2(float x0, float x1, uint32_t& hp, uint32_t& lp) {
    __nv_bfloat16 h0 = __float2bfloat16(x0), h1 = __float2bfloat16(x1);
    __nv_bfloat162 hh(h0, h1);
    hp = *reinterpret_cast<uint32_t*>(&hh);
    __nv_bfloat16 l0 = __float2bfloat16(x0 - __bfloat162float(h0));
    __nv_bfloat16 l1 = __float2bfloat16(x1 - __bfloat162float(h1));
    __nv_bfloat162 ll(l0, l1);
    lp = *reinterpret_cast<uint32_t*>(&ll);
}

// =================================================================
//   HMMA split-bf16 GEMM 128x128 — single barrier per K-chunk.
//   Split-K via blockIdx.z (EPI 5 = atomicAdd partial into C).
// =================================================================
#define SROW 40
#define STILE (128 * SROW)
#define SMEM_MMA_BYTES (2 * 4 * STILE * 2)

template <int EPI>
__global__ void __launch_bounds__(256, 2)
gemm_mma(const __nv_bfloat16* __restrict__ Ah, const __nv_bfloat16* __restrict__ Al,
         const __nv_bfloat16* __restrict__ Bh, const __nv_bfloat16* __restrict__ Bl,
         const float* __restrict__ Add, float* __restrict__ C,
         int N, int K, int ldc) {
    extern __shared__ __nv_bfloat16 smh[];
    int tid = threadIdx.x;
    int wid = tid >> 5, lane = tid & 31;
    int wm = wid >> 1, wn = wid & 1;
    int lr = lane >> 2, lc = lane & 3;

    int m0 = blockIdx.y * 128;
    int n0 = blockIdx.x * 128;
    int ksplit = K / (int)gridDim.z;
    int kbase = (int)blockIdx.z * ksplit;

    const __nv_bfloat16* srcs[4] = {
        Ah + (size_t)m0 * K, Al + (size_t)m0 * K,
        Bh + (size_t)n0 * K, Bl + (size_t)n0 * K};

    int lrow = tid >> 1;
    int q0 = (tid & 1) * 2;
    int nch = ksplit >> 5;

    uint32_t sbu = smem_u32(smh);
    uint32_t a_lane = (uint32_t)((lane & 15) * SROW + (lane >> 4) * 8);
    uint32_t b_lane = (uint32_t)((((lane >> 4) << 3) + (lane & 7)) * SROW + ((lane >> 3) & 1) * 8);

    {
#pragma unroll
        for (int t = 0; t < 4; t++) {
            const __nv_bfloat16* sp = srcs[t] + (size_t)lrow * K + kbase;
            __nv_bfloat16* dp = smh + t * STILE + lrow * SROW;
            cpa16(dp + q0 * 8, sp + q0 * 8);
            cpa16(dp + (q0 + 1) * 8, sp + (q0 + 1) * 8);
        }
        asm volatile("cp.async.commit_group;");
    }

    float acc[2][8][4];
#pragma unroll
    for (int i = 0; i < 2; i++)
#pragma unroll
        for (int j = 0; j < 8; j++)
#pragma unroll
            for (int r = 0; r < 4; r++) acc[i][j][r] = 0.f;

    for (int c = 0; c < nch; c++) {
        asm volatile("cp.async.wait_group 0;");
        __syncthreads();
        if (c + 1 < nch) {
            int k0 = kbase + ((c + 1) << 5);
            __nv_bfloat16* sb = smh + ((c + 1) & 1) * 4 * STILE;
#pragma unroll
            for (int t = 0; t < 4; t++) {
                const __nv_bfloat16* sp = srcs[t] + (size_t)lrow * K + k0;
                __nv_bfloat16* dp = sb + t * STILE + lrow * SROW;
                cpa16(dp + q0 * 8, sp + q0 * 8);
                cpa16(dp + (q0 + 1) * 8, sp + (q0 + 1) * 8);
            }
            asm volatile("cp.async.commit_group;");
        }

        uint32_t tbu = sbu + (uint32_t)((c & 1) * 4 * STILE) * 2u;
        uint32_t pAh = tbu;
        uint32_t pAl = tbu + STILE * 2u;
        uint32_t pBh = tbu + 2u * STILE * 2u;
        uint32_t pBl = tbu + 3u * STILE * 2u;

#pragma unroll
        for (int ks = 0; ks < 2; ks++) {
            uint32_t kso = (uint32_t)(ks * 16) * 2u;
            uint32_t ah[2][4], al[2][4], bh[8][2], bl[8][2];
#pragma unroll
            for (int i = 0; i < 2; i++) {
                uint32_t off = (uint32_t)((wm * 32 + i * 16) * SROW) * 2u + a_lane * 2u + kso;
                ldsm_x4(ah[i], pAh + off);
                ldsm_x4(al[i], pAl + off);
            }
#pragma unroll
            for (int jp = 0; jp < 4; jp++) {
                uint32_t off = (uint32_t)((wn * 64 + jp * 16) * SROW) * 2u + b_lane * 2u + kso;
                uint32_t q[4];
                ldsm_x4(q, pBh + off);
                bh[2 * jp][0] = q[0]; bh[2 * jp][1] = q[1];
                bh[2 * jp + 1][0] = q[2]; bh[2 * jp + 1][1] = q[3];
                ldsm_x4(q, pBl + off);
                bl[2 * jp][0] = q[0]; bl[2 * jp][1] = q[1];
                bl[2 * jp + 1][0] = q[2]; bl[2 * jp + 1][1] = q[3];
            }
#pragma unroll
            for (int i = 0; i < 2; i++)
#pragma unroll
                for (int j = 0; j < 8; j++) mma_bf16(acc[i][j], ah[i], bh[j]);
#pragma unroll
            for (int i = 0; i < 2; i++)
#pragma unroll
                for (int j = 0; j < 8; j++) mma_bf16(acc[i][j], ah[i], bl[j]);
#pragma unroll
            for (int i = 0; i < 2; i++)
#pragma unroll
                for (int j = 0; j < 8; j++) mma_bf16(acc[i][j], al[i], bh[j]);
        }
    }

#pragma unroll
    for (int i = 0; i < 2; i++) {
#pragma unroll
        for (int half = 0; half < 2; half++) {
            int r = m0 + wm * 32 + i * 16 + lr + half * 8;
#pragma unroll
            for (int j = 0; j < 8; j++) {
                int col = n0 + wn * 64 + j * 8 + lc * 2;
                float v0 = acc[i][j][half * 2 + 0];
                float v1 = acc[i][j][half * 2 + 1];
                if (EPI == 0) {
                    float* crow = C + (size_t)r * ldc;
                    if (col < N) crow[col] = v0;
                    if (col + 1 < N) crow[col + 1] = v1;
                } else if (EPI == 5) {
                    // split-K partial: accumulate onto residual already in C
                    atomicAdd(C + (size_t)r * ldc + col, v0);
                    atomicAdd(C + (size_t)r * ldc + col + 1, v1);
                } else if (EPI == 3) {
                    int b = r >> 10, t = r & 1023;
                    int seg = col >> 9, cc = col & 511;
                    int hh = cc >> 6, d = cc & 63;
                    size_t bht = (((size_t)(b * 8 + hh)) << 10) + t;
                    uint32_t hp, lp;
                    if (seg == 0) {
                        v0 *= 0.125f; v1 *= 0.125f;
                        split2(v0, v1, hp, lp);
                        *reinterpret_cast<uint32_t*>(g_qh + bht * 64 + d) = hp;
                        *reinterpret_cast<uint32_t*>(g_ql + bht * 64 + d) = lp;
                    } else if (seg == 1) {
                        split2(v0, v1, hp, lp);
                        *reinterpret_cast<uint32_t*>(g_kh + bht * 64 + d) = hp;
                        *reinterpret_cast<uint32_t*>(g_kl + bht * 64 + d) = lp;
                    } else {
                        split2(v0, v1, hp, lp);
                        *reinterpret_cast<uint32_t*>(g_vh + bht * 64 + d) = hp;
                        *reinterpret_cast<uint32_t*>(g_vl + bht * 64 + d) = lp;
                    }
                } else if (EPI == 4) {
                    v0 = 0.5f * v0 * (1.f + erff(v0 * 0.70710678118654752440f));
                    v1 = 0.5f * v1 * (1.f + erff(v1 * 0.70710678118654752440f));
                    uint32_t hp, lp; split2(v0, v1, hp, lp);
                    size_t off = (size_t)r * 2048 + col;
                    *reinterpret_cast<uint32_t*>(g_h2h + off) = hp;
                    *reinterpret_cast<uint32_t*>(g_h2l + off) = lp;
                }
            }
        }
    }
}

// =================================================================
//    Fused flash attention (R16-proven: single barrier, warp skip)
// =================================================================
#define AT_SMEM 73728

__device__ __forceinline__ void at_load_kv(
    __nv_bfloat16* sm, int tid,
    const __nv_bfloat16* kh, const __nv_bfloat16* kl,
    const __nv_bfloat16* vh, const __nv_bfloat16* vl,
    size_t qkoff, int kb, int bsel) {
    int row = tid >> 1;
    int q0 = (tid & 1) * 4;
    __nv_bfloat16* base = sm + bsel * 18432;
    const __nv_bfloat16* gkh = kh + qkoff + (size_t)(kb * 64 + row) * 64;
    const __nv_bfloat16* gkl = kl + qkoff + (size_t)(kb * 64 + row) * 64;
    const __nv_bfloat16* gvh = vh + qkoff + (size_t)(kb * 64 + row) * 64;
    const __nv_bfloat16* gvl = vl + qkoff + (size_t)(kb * 64 + row) * 64;
#pragma unroll
    for (int c = 0; c < 4; c++) {
        cpa16(base + row * 72 + (q0 + c) * 8, gkh + (q0 + c) * 8);
        cpa16(base + 4608 + row * 72 + (q0 + c) * 8, gkl + (q0 + c) * 8);
        cpa16(base + 9216 + row * 72 + (q0 + c) * 8, gvh + (q0 + c) * 8);
        cpa16(base + 13824 + row * 72 + (q0 + c) * 8, gvl + (q0 + c) * 8);
    }
}

__global__ void __launch_bounds__(128)
flash_attn(const __nv_bfloat16* __restrict__ qh, const __nv_bfloat16* __restrict__ ql,
           const __nv_bfloat16* __restrict__ kh, const __nv_bfloat16* __restrict__ kl,
           const __nv_bfloat16* __restrict__ vh, const __nv_bfloat16* __restrict__ vl,
           __nv_bfloat16* __restrict__ yh, __nv_bfloat16* __restrict__ yl) {
    extern __shared__ __nv_bfloat16 sm[];
    int tid = threadIdx.x, w = tid >> 5, lane = tid & 31;
    int lr = lane >> 2, lc = lane & 3;
    int qb = 7 - blockIdx.x;
    int bh = blockIdx.y;
    const size_t qkoff = (size_t)bh << 16;

    uint32_t smu = smem_u32(sm);
    uint32_t b_lane72 = (uint32_t)((((lane >> 4) << 3) + (lane & 7)) * 72 + ((lane >> 3) & 1) * 8);
    uint32_t a_lane72 = (uint32_t)((lane & 15) * 72 + (lane >> 4) * 8);

    {
        const __nv_bfloat16* gq = qh + qkoff + (size_t)(qb * 128 + tid) * 64;
        const __nv_bfloat16* gq2 = ql + qkoff + (size_t)(qb * 128 + tid) * 64;
        __nv_bfloat16* dh = sm + tid * 72;
        __nv_bfloat16* dl = sm + 9216 + tid * 72;
#pragma unroll
        for (int q = 0; q < 8; q++) { cpa16(dh + q * 8, gq + q * 8); cpa16(dl + q * 8, gq2 + q * 8); }
        asm volatile("cp.async.commit_group;");
        asm volatile("cp.async.wait_group 0;");
        __syncthreads();
    }
    uint32_t qfh[2][4][4], qfl[2][4][4];
#pragma unroll
    for (int mt = 0; mt < 2; mt++)
#pragma unroll
        for (int kk = 0; kk < 4; kk++) {
            int r = w * 32 + mt * 16 + lr;
            const __nv_bfloat16* p = sm + r * 72 + kk * 16 + lc * 2;
            qfh[mt][kk][0] = *(const uint32_t*)p;
            qfh[mt][kk][1] = *(const uint32_t*)(p + 8 * 72);
            qfh[mt][kk][2] = *(const uint32_t*)(p + 8);
            qfh[mt][kk][3] = *(const uint32_t*)(p + 8 * 72 + 8);
            const __nv_bfloat16* p2 = p + 9216;
            qfl[mt][kk][0] = *(const uint32_t*)p2;
            qfl[mt][kk][1] = *(const uint32_t*)(p2 + 8 * 72);
            qfl[mt][kk][2] = *(const uint32_t*)(p2 + 8);
            qfl[mt][kk][3] = *(const uint32_t*)(p2 + 8 * 72 + 8);
        }
    __syncthreads();

    float m_[4], l_[4], o[2][8][4];
#pragma unroll
    for (int s = 0; s < 4; s++) { m_[s] = -1e30f; l_[s] = 0.f; }
#pragma unroll
    for (int i = 0; i < 2; i++)
#pragma unroll
        for (int j = 0; j < 8; j++)
#pragma unroll
            for (int r = 0; r < 4; r++) o[i][j][r] = 0.f;

    int nkb = 2 * qb + 2;
    at_load_kv(sm, tid, kh, kl, vh, vl, qkoff, 0, 1);
    asm volatile("cp.async.commit_group;");

    for (int kb = 0; kb < nkb; kb++) {
        asm volatile("cp.async.wait_group 0;");
        __syncthreads();
        if (kb + 1 < nkb) {
            at_load_kv(sm, tid, kh, kl, vh, vl, qkoff, kb + 1, kb & 1);
            asm volatile("cp.async.commit_group;");
        }

        bool active = !(kb == 2 * qb + 1 && w < 2);
        bool need_mask = (kb == 2 * qb && w < 2) || (kb == 2 * qb + 1 && w >= 2);

        if (active) {
            uint32_t bb = smu + (uint32_t)(((kb + 1) & 1) * 18432) * 2u;
            uint32_t pKh = bb;
            uint32_t pKl = bb + 4608 * 2u;
            uint32_t pVh = bb + 9216 * 2u;
            uint32_t pVl = bb + 13824 * 2u;

            float s[2][8][4];
#pragma unroll
            for (int i = 0; i < 2; i++)
#pragma unroll
                for (int j = 0; j < 8; j++)
#pragma unroll
                    for (int r = 0; r < 4; r++) s[i][j][r] = 0.f;

#pragma unroll
            for (int kk = 0; kk < 4; kk++) {
                uint32_t kso = (uint32_t)(kk * 16) * 2u;
                uint32_t bh_[8][2], bl_[8][2];
#pragma unroll
                for (int jp = 0; jp < 4; jp++) {
                    uint32_t off = (uint32_t)(jp * 16 * 72) * 2u + b_lane72 * 2u + kso;
                    uint32_t q[4];
                    ldsm_x4(q, pKh + off);
                    bh_[2 * jp][0] = q[0]; bh_[2 * jp][1] = q[1];
                    bh_[2 * jp + 1][0] = q[2]; bh_[2 * jp + 1][1] = q[3];
                    ldsm_x4(q, pKl + off);
                    bl_[2 * jp][0] = q[0]; bl_[2 * jp][1] = q[1];
                    bl_[2 * jp + 1][0] = q[2]; bl_[2 * jp + 1][1] = q[3];
                }
#pragma unroll
                for (int jn = 0; jn < 8; jn++)
#pragma unroll
                    for (int mt = 0; mt < 2; mt++) {
                        mma_bf16(s[mt][jn], qfh[mt][kk], bh_[jn]);
                        mma_bf16(s[mt][jn], qfh[mt][kk], bl_[jn]);
                        mma_bf16(s[mt][jn], qfl[mt][kk], bh_[jn]);
                    }
            }

            if (need_mask) {
                int rowbase = qb * 128 + w * 32;
                int colbase = kb * 64;
#pragma unroll
                for (int mt = 0; mt < 2; mt++)
#pragma unroll
                    for (int jn = 0; jn < 8; jn++)
#pragma unroll
                        for (int idx = 0; idx < 4; idx++) {
                            int row = rowbase + mt * 16 + lr + ((idx >> 1) << 3);
                            int col = colbase + jn * 8 + lc * 2 + (idx & 1);
                            if (col > row) s[mt][jn][idx] = -1e30f;
                        }
            }

            float scl[4];
#pragma unroll
            for (int sl = 0; sl < 4; sl++) {
                int mt = sl >> 1, h = sl & 1;
                float cm = -1e30f;
#pragma unroll
                for (int jn = 0; jn < 8; jn++)
                    cm = fmaxf(cm, fmaxf(s[mt][jn][h * 2], s[mt][jn][h * 2 + 1]));
                cm = fmaxf(cm, __shfl_xor_sync(0xffffffffu, cm, 1));
                cm = fmaxf(cm, __shfl_xor_sync(0xffffffffu, cm, 2));
                float mnew = fmaxf(m_[sl], cm);
                scl[sl] = __expf(m_[sl] - mnew);
                m_[sl] = mnew;
            }
            float rs[4] = {0.f, 0.f, 0.f, 0.f};
#pragma unroll
            for (int mt = 0; mt < 2; mt++)
#pragma unroll
                for (int jn = 0; jn < 8; jn++) {
                    s[mt][jn][0] = __expf(s[mt][jn][0] - m_[mt * 2]);
                    s[mt][jn][1] = __expf(s[mt][jn][1] - m_[mt * 2]);
                    s[mt][jn][2] = __expf(s[mt][jn][2] - m_[mt * 2 + 1]);
                    s[mt][jn][3] = __expf(s[mt][jn][3] - m_[mt * 2 + 1]);
                    rs[mt * 2] += s[mt][jn][0] + s[mt][jn][1];
                    rs[mt * 2 + 1] += s[mt][jn][2] + s[mt][jn][3];
                }
#pragma unroll
            for (int sl = 0; sl < 4; sl++) {
                rs[sl] += __shfl_xor_sync(0xffffffffu, rs[sl], 1);
                rs[sl] += __shfl_xor_sync(0xffffffffu, rs[sl], 2);
                l_[sl] = l_[sl] * scl[sl] + rs[sl];
            }
#pragma unroll
            for (int mt = 0; mt < 2; mt++)
#pragma unroll
                for (int jn = 0; jn < 8; jn++) {
                    o[mt][jn][0] *= scl[mt * 2];
                    o[mt][jn][1] *= scl[mt * 2];
                    o[mt][jn][2] *= scl[mt * 2 + 1];
                    o[mt][jn][3] *= scl[mt * 2 + 1];
                }

#pragma unroll
            for (int kk = 0; kk < 4; kk++) {
                uint32_t pah[2][4], pal[2][4];
#pragma unroll
                for (int mt = 0; mt < 2; mt++) {
                    split2(s[mt][2 * kk][0], s[mt][2 * kk][1], pah[mt][0], pal[mt][0]);
                    split2(s[mt][2 * kk][2], s[mt][2 * kk][3], pah[mt][1], pal[mt][1]);
                    split2(s[mt][2 * kk + 1][0], s[mt][2 * kk + 1][1], pah[mt][2], pal[mt][2]);
                    split2(s[mt][2 * kk + 1][2], s[mt][2 * kk + 1][3], pah[mt][3], pal[mt][3]);
                }
                uint32_t vh_[8][2], vl_[8][2];
#pragma unroll
                for (int jp = 0; jp < 4; jp++) {
                    uint32_t off = (uint32_t)(kk * 16 * 72 + jp * 16) * 2u + a_lane72 * 2u;
                    uint32_t q[4];
                    ldsm_x4_t(q, pVh + off);
                    vh_[2 * jp][0] = q[0]; vh_[2 * jp][1] = q[1];
                    vh_[2 * jp + 1][0] = q[2]; vh_[2 * jp + 1][1] = q[3];
                    ldsm_x4_t(q, pVl + off);
                    vl_[2 * jp][0] = q[0]; vl_[2 * jp][1] = q[1];
                    vl_[2 * jp + 1][0] = q[2]; vl_[2 * jp + 1][1] = q[3];
                }
#pragma unroll
                for (int jn = 0; jn < 8; jn++)
#pragma unroll
                    for (int mt = 0; mt < 2; mt++) {
                        mma_bf16(o[mt][jn], pah[mt], vh_[jn]);
                        mma_bf16(o[mt][jn], pah[mt], vl_[jn]);
                        mma_bf16(o[mt][jn], pal[mt], vh_[jn]);
                    }
            }
        }
    }

    int b = bh >> 3, hhd = bh & 7;
#pragma unroll
    for (int mt = 0; mt < 2; mt++)
#pragma unroll
        for (int h = 0; h < 2; h++) {
            int t = qb * 128 + w * 32 + mt * 16 + lr + h * 8;
            size_t row = (size_t)(b * 1024 + t) * 512 + hhd * 64;
            float inv = 1.f / l_[mt * 2 + h];
#pragma unroll
            for (int jn = 0; jn < 8; jn++) {
                int col = jn * 8 + lc * 2;
                float x0 = o[mt][jn][h * 2] * inv;
                float x1 = o[mt][jn][h * 2 + 1] * inv;
                uint32_t hp, lp;
                split2(x0, x1, hp, lp);
                *reinterpret_cast<uint32_t*>(yh + row + col) = hp;
                *reinterpret_cast<uint32_t*>(yl + row + col) = lp;
            }
        }
}

// ---------------- fp32 -> bf16 hi/lo split (weights/wte only) ----------------
__global__ void split_act(const float4* __restrict__ x, __nv_bfloat16* __restrict__ hi,
                          __nv_bfloat16* __restrict__ lo, int n4) {
    int i = blockIdx.x * blockDim.x + threadIdx.x;
    if (i >= n4) return;
    float4 v = x[i];
    uint32_t hp, lp;
    split2(v.x, v.y, hp, lp);
    reinterpret_cast<uint32_t*>(hi)[2 * i] = hp;
    reinterpret_cast<uint32_t*>(lo)[2 * i] = lp;
    split2(v.z, v.w, hp, lp);
    reinterpret_cast<uint32_t*>(hi)[2 * i + 1] = hp;
    reinterpret_cast<uint32_t*>(lo)[2 * i + 1] = lp;
}

// ---------------- weight split + transpose: W[K,N] fp32 -> hi/lo [N,K] bf16 ----------------
__global__ void split_wT(const float* __restrict__ w, __nv_bfloat16* __restrict__ hi,
                         __nv_bfloat16* __restrict__ lo, int K, int N) {
    __shared__ float t[32][33];
    int z = blockIdx.z;
    w += (size_t)z * K * N;
    hi += (size_t)z * N * K;
    lo += (size_t)z * N * K;
    int n0 = blockIdx.x * 32, k0 = blockIdx.y * 32;
    int tx = threadIdx.x, ty = threadIdx.y;
#pragma unroll
    for (int j = 0; j < 4; j++)
        t[ty + j * 8][tx] = w[(size_t)(k0 + ty + j * 8) * N + n0 + tx];
    __syncthreads();
#pragma unroll
    for (int j = 0; j < 4; j++) {
        int n = n0 + ty + j * 8, k = k0 + tx;
        float v = t[tx][ty + j * 8];
        __nv_bfloat16 h = __float2bfloat16(v);
        hi[(size_t)n * K + k] = h;
        lo[(size_t)n * K + k] = __float2bfloat16(v - __bfloat162float(h));
    }
}

// ---------------- embedding ----------------
__global__ void embed_kernel(const int* __restrict__ idx,
                             const float* __restrict__ wte,
                             const float* __restrict__ wpe,
                             float* __restrict__ out) {
    int t = blockIdx.x;
    int pos = t % T_;
    int id = idx[t];
    float4 a = reinterpret_cast<const float4*>(wte + (long long)id * E_)[threadIdx.x];
    float4 b = reinterpret_cast<const float4*>(wpe + (long long)pos * E_)[threadIdx.x];
    float4 o;
    o.x = a.x + b.x; o.y = a.y + b.y; o.z = a.z + b.z; o.w = a.w + b.w;
    reinterpret_cast<float4*>(out + (long long)t * E_)[threadIdx.x] = o;
}

// ---------------- LayerNorm -> split bf16 ----------------
__global__ void ln_split(const float* __restrict__ x, const float* __restrict__ w,
                         __nv_bfloat16* __restrict__ oh, __nv_bfloat16* __restrict__ ol) {
    int row = blockIdx.x;
    float4 v = reinterpret_cast<const float4*>(x + (long long)row * E_)[threadIdx.x];
    float s = v.x + v.y + v.z + v.w;
    float ss = v.x * v.x + v.y * v.y + v.z * v.z + v.w * v.w;
    __shared__ float sh[8];
#pragma unroll
    for (int o = 16; o > 0; o >>= 1) {
        s += __shfl_down_sync(0xffffffffu, s, o);
        ss += __shfl_down_sync(0xffffffffu, ss, o);
    }
    int wid = threadIdx.x >> 5, lane = threadIdx.x & 31;
    if (lane == 0) { sh[wid] = s; sh[4 + wid] = ss; }
    __syncthreads();
    if (threadIdx.x == 0) {
        float ts = sh[0] + sh[1] + sh[2] + sh[3];
        float tss = sh[4] + sh[5] + sh[6] + sh[7];
        float m = ts * (1.f / E_);
        float var = tss * (1.f / E_) - m * m;
        sh[0] = m;
        sh[1] = rsqrtf(var + 1e-5f);
    }
    __syncthreads();
    float m = sh[0], r = sh[1];
    float4 wv = reinterpret_cast<const float4*>(w)[threadIdx.x];
    float o0 = (v.x - m) * r * wv.x;
    float o1 = (v.y - m) * r * wv.y;
    float o2 = (v.z - m) * r * wv.z;
    float o3 = (v.w - m) * r * wv.w;
    size_t base = (size_t)row * E_ + threadIdx.x * 4;
    uint32_t hp, lp;
    split2(o0, o1, hp, lp);
    *reinterpret_cast<uint32_t*>(oh + base) = hp;
    *reinterpret_cast<uint32_t*>(ol + base) = lp;
    split2(o2, o3, hp, lp);
    *reinterpret_cast<uint32_t*>(oh + base + 2) = hp;
    *reinterpret_cast<uint32_t*>(ol + base + 2) = lp;
}

// =================================================================
//                          host pipeline
// =================================================================
extern "C" void kernel_launch(void* const* d_in, const int* in_sizes, int n_in,
                              void* d_out, int out_size) {
    (void)in_sizes; (void)n_in; (void)out_size;
    const int* idx = (const int*)d_in[0];
    const float* wte = (const float*)d_in[1];
    const float* wpe = (const float*)d_in[2];
    const float* aw = (const float*)d_in[3];
    const float* pw = (const float*)d_in[4];
    const float* fw = (const float*)d_in[5];
    const float* fpw = (const float*)d_in[6];
    const float* l1 = (const float*)d_in[7];
    const float* l2 = (const float*)d_in[8];
    const float* lnf = (const float*)d_in[9];
    float* out = (float*)d_out;

    float* gx;
    __nv_bfloat16 *glnh, *glnl, *gqh, *gql, *gkh, *gkl, *gvh, *gvl, *gyh, *gyl, *gh2h, *gh2l, *gwh, *gwl;
    cudaGetSymbolAddress((void**)&gx, g_x);
    cudaGetSymbolAddress((void**)&glnh, g_lnh);
    cudaGetSymbolAddress((void**)&glnl, g_lnl);
    cudaGetSymbolAddress((void**)&gqh, g_qh);
    cudaGetSymbolAddress((void**)&gql, g_ql);
    cudaGetSymbolAddress((void**)&gkh, g_kh);
    cudaGetSymbolAddress((void**)&gkl, g_kl);
    cudaGetSymbolAddress((void**)&gvh, g_vh);
    cudaGetSymbolAddress((void**)&gvl, g_vl);
    cudaGetSymbolAddress((void**)&gyh, g_yh);
    cudaGetSymbolAddress((void**)&gyl, g_yl);
    cudaGetSymbolAddress((void**)&gh2h, g_h2h);
    cudaGetSymbolAddress((void**)&gh2l, g_h2l);
    cudaGetSymbolAddress((void**)&gwh, g_wh);
    cudaGetSymbolAddress((void**)&gwl, g_wl);

    cudaFuncSetAttribute(gemm_mma<0>, cudaFuncAttributeMaxDynamicSharedMemorySize, SMEM_MMA_BYTES);
    cudaFuncSetAttribute(gemm_mma<3>, cudaFuncAttributeMaxDynamicSharedMemorySize, SMEM_MMA_BYTES);
    cudaFuncSetAttribute(gemm_mma<4>, cudaFuncAttributeMaxDynamicSharedMemorySize, SMEM_MMA_BYTES);
    cudaFuncSetAttribute(gemm_mma<5>, cudaFuncAttributeMaxDynamicSharedMemorySize, SMEM_MMA_BYTES);
    cudaFuncSetAttribute(flash_attn, cudaFuncAttributeMaxDynamicSharedMemorySize, AT_SMEM);

    dim3 b32(32, 8);
    split_wT<<<dim3(3 * E_ / 32, E_ / 32, L_), b32>>>(aw, gwh + OFF_AW, gwl + OFF_AW, E_, 3 * E_);
    split_wT<<<dim3(E_ / 32, E_ / 32, L_), b32>>>(pw, gwh + OFF_PW, gwl + OFF_PW, E_, E_);
    split_wT<<<dim3(4 * E_ / 32, E_ / 32, L_), b32>>>(fw, gwh + OFF_FW, gwl + OFF_FW, E_, 4 * E_);
    split_wT<<<dim3(E_ / 32, 4 * E_ / 32, L_), b32>>>(fpw, gwh + OFF_FPW, gwl + OFF_FPW, 4 * E_, E_);
    split_act<<<(V_ * E_ / 4 + 255) / 256, 256>>>((const float4*)wte, gwh + OFF_WTE, gwl + OFF_WTE, V_ * E_ / 4);

    embed_kernel<<<B_ * T_, 128>>>(idx, wte, wpe, gx);

    for (int l = 0; l < L_; l++) {
        ln_split<<<B_ * T_, 128>>>(gx, l1 + (long long)l * E_, glnh, glnl);
        gemm_mma<3><<<dim3(12, 32), 256, SMEM_MMA_BYTES>>>(
            glnh, glnl, gwh + OFF_AW + (size_t)l * 3 * E_ * E_, gwl + OFF_AW + (size_t)l * 3 * E_ * E_,
            nullptr, gx, 1536, 512, 1536);
        flash_attn<<<dim3(8, 32), 128, AT_SMEM>>>(gqh, gql, gkh, gkl, gvh, gvl, gyh, gyl);
        // x += y @ pw[l]  (split-K=2, atomic accumulate onto residual)
        gemm_mma<5><<<dim3(4, 32, 2), 256, SMEM_MMA_BYTES>>>(
            gyh, gyl, gwh + OFF_PW + (size_t)l * E_ * E_, gwl + OFF_PW + (size_t)l * E_ * E_,
            nullptr, gx, 512, 512, 512);
        ln_split<<<B_ * T_, 128>>>(gx, l2 + (long long)l * E_, glnh, glnl);
        gemm_mma<4><<<dim3(16, 32), 256, SMEM_MMA_BYTES>>>(
            glnh, glnl, gwh + OFF_FW + (size_t)l * 4 * E_ * E_, gwl + OFF_FW + (size_t)l * 4 * E_ * E_,
            nullptr, gx, 2048, 512, 2048);
        // x += h2 @ fpw[l]  (split-K=4, atomic accumulate onto residual)
        gemm_mma<5><<<dim3(4, 32, 4), 256, SMEM_MMA_BYTES>>>(
            gh2h, gh2l, gwh + OFF_FPW + (size_t)l * E_ * 4 * E_, gwl + OFF_FPW + (size_t)l * E_ * 4 * E_,
            nullptr, gx, 512, 2048, 512);
    }

    ln_split<<<B_ * T_, 128>>>(gx, lnf, glnh, glnl);
    gemm_mma<0><<<dim3(3, 32), 256, SMEM_MMA_BYTES>>>(
        glnh, glnl, gwh + OFF_WTE, gwl + OFF_WTE,
        nullptr, out, V_, 512, V_);
}